// round 1
// baseline (speedup 1.0000x reference)
#include <cuda_runtime.h>
#include <math.h>

// Problem constants: B=8, S=1024, D=768, H=12, DH=64
#define NB 8
#define NS 1024
#define ND 768
#define NH 12
#define NDH 64
#define NROWS (NB * NS)          // 8192
#define DFF (4 * ND)             // 3072

// ---------------- scratch (device globals: no allocation allowed) ----------
__device__ float g_ln1[NROWS * ND];       // 25.2 MB
__device__ float g_q[NROWS * ND];         // [B,H,S,DH]
__device__ float g_k[NROWS * ND];
__device__ float g_v[NROWS * ND];
__device__ float g_ln2[NROWS * ND];
__device__ float g_hid[NROWS * DFF];      // 100.7 MB

// ---------------- LayerNorm: one block per row ------------------------------
__global__ __launch_bounds__(256) void ln_kernel(
    const float* __restrict__ x, const float* __restrict__ gw,
    const float* __restrict__ bw, float* __restrict__ out)
{
    __shared__ float r1[8], r2[8];
    int row = blockIdx.x, t = threadIdx.x;
    const float* xr = x + (size_t)row * ND;
    float v0 = xr[t], v1 = xr[t + 256], v2 = xr[t + 512];
    float s = v0 + v1 + v2;
#pragma unroll
    for (int o = 16; o > 0; o >>= 1) s += __shfl_xor_sync(0xffffffffu, s, o);
    if ((t & 31) == 0) r1[t >> 5] = s;
    __syncthreads();
    float tot = r1[0] + r1[1] + r1[2] + r1[3] + r1[4] + r1[5] + r1[6] + r1[7];
    float mean = tot * (1.0f / (float)ND);
    float d0 = v0 - mean, d1 = v1 - mean, d2 = v2 - mean;
    float sq = d0 * d0 + d1 * d1 + d2 * d2;
#pragma unroll
    for (int o = 16; o > 0; o >>= 1) sq += __shfl_xor_sync(0xffffffffu, sq, o);
    if ((t & 31) == 0) r2[t >> 5] = sq;
    __syncthreads();
    float var = (r2[0] + r2[1] + r2[2] + r2[3] + r2[4] + r2[5] + r2[6] + r2[7]) * (1.0f / (float)ND);
    float rstd = rsqrtf(var + 1e-5f);
    float* orow = out + (size_t)row * ND;
    orow[t]       = d0 * rstd * gw[t]       + bw[t];
    orow[t + 256] = d1 * rstd * gw[t + 256] + bw[t + 256];
    orow[t + 512] = d2 * rstd * gw[t + 512] + bw[t + 512];
}

// ---------------- QKV: per-head 64x64 projections ---------------------------
// grid (B*H, S/64), 256 threads. Dynamic smem: Wq,Wk,Wv (4096 fl each) + x tile (64x68)
__global__ __launch_bounds__(256) void qkv_kernel(
    const float* __restrict__ ln1,
    const float* __restrict__ Wq, const float* __restrict__ bq,
    const float* __restrict__ Wk, const float* __restrict__ bk,
    const float* __restrict__ Wv, const float* __restrict__ bv,
    float* __restrict__ q, float* __restrict__ k, float* __restrict__ v)
{
    extern __shared__ float sm[];
    float* sWq = sm;
    float* sWk = sm + 4096;
    float* sWv = sm + 8192;
    float* xs  = sm + 12288;   // 64 x 68 (padded)

    int bh = blockIdx.x;
    int h = bh % NH, b = bh / NH;
    int s0 = blockIdx.y * 64;
    int t = threadIdx.x;

    const float4* wq4 = (const float4*)(Wq + (size_t)h * 4096);
    const float4* wk4 = (const float4*)(Wk + (size_t)h * 4096);
    const float4* wv4 = (const float4*)(Wv + (size_t)h * 4096);
#pragma unroll
    for (int i = 0; i < 4; i++) {
        ((float4*)sWq)[t + i * 256] = wq4[t + i * 256];
        ((float4*)sWk)[t + i * 256] = wk4[t + i * 256];
        ((float4*)sWv)[t + i * 256] = wv4[t + i * 256];
    }
#pragma unroll
    for (int i = 0; i < 4; i++) {
        int f = t + i * 256;              // 0..1023 float4s
        int r = f >> 4, c = f & 15;
        float4 xv = *(const float4*)(ln1 + ((size_t)(b * NS + s0 + r)) * ND + h * NDH + c * 4);
        *(float4*)(xs + r * 68 + c * 4) = xv;
    }
    __syncthreads();

    int r = t >> 2, ec = (t & 3) * 16;
    float aq[16], ak[16], av[16];
#pragma unroll
    for (int i = 0; i < 16; i++) {
        aq[i] = bq[h * NDH + ec + i];
        ak[i] = bk[h * NDH + ec + i];
        av[i] = bv[h * NDH + ec + i];
    }
    for (int d = 0; d < 64; d++) {
        float xv = xs[r * 68 + d];
#pragma unroll
        for (int i4 = 0; i4 < 4; i4++) {
            float4 wq = *(const float4*)(sWq + d * 64 + ec + i4 * 4);
            float4 wk = *(const float4*)(sWk + d * 64 + ec + i4 * 4);
            float4 wv = *(const float4*)(sWv + d * 64 + ec + i4 * 4);
            aq[i4 * 4 + 0] += xv * wq.x; aq[i4 * 4 + 1] += xv * wq.y;
            aq[i4 * 4 + 2] += xv * wq.z; aq[i4 * 4 + 3] += xv * wq.w;
            ak[i4 * 4 + 0] += xv * wk.x; ak[i4 * 4 + 1] += xv * wk.y;
            ak[i4 * 4 + 2] += xv * wk.z; ak[i4 * 4 + 3] += xv * wk.w;
            av[i4 * 4 + 0] += xv * wv.x; av[i4 * 4 + 1] += xv * wv.y;
            av[i4 * 4 + 2] += xv * wv.z; av[i4 * 4 + 3] += xv * wv.w;
        }
    }
    size_t ob = ((size_t)bh * NS + s0 + r) * NDH + ec;
#pragma unroll
    for (int i4 = 0; i4 < 4; i4++) {
        *(float4*)(q + ob + i4 * 4) = make_float4(aq[i4 * 4], aq[i4 * 4 + 1], aq[i4 * 4 + 2], aq[i4 * 4 + 3]);
        *(float4*)(k + ob + i4 * 4) = make_float4(ak[i4 * 4], ak[i4 * 4 + 1], ak[i4 * 4 + 2], ak[i4 * 4 + 3]);
        *(float4*)(v + ob + i4 * 4) = make_float4(av[i4 * 4], av[i4 * 4 + 1], av[i4 * 4 + 2], av[i4 * 4 + 3]);
    }
}

// ---------------- Attention (flash-style, non-causal) -----------------------
// grid (B*H, S/128), 128 threads; each thread owns one query row.
// Dynamic smem: Ks[64*64] + Vs[64*64] + scores[128*65]
__global__ __launch_bounds__(128) void attn_kernel(
    const float* __restrict__ q, const float* __restrict__ k,
    const float* __restrict__ v, const float* __restrict__ x,
    float* __restrict__ out)
{
    extern __shared__ float sm[];
    float* Ks = sm;
    float* Vs = sm + 4096;
    float* ss = sm + 8192;   // 128 rows x 65

    int bh = blockIdx.x;
    int h = bh % NH, b = bh / NH;
    int t = threadIdx.x;
    int qrow = blockIdx.y * 128 + t;

    float4 qr[16];
    const float4* qg = (const float4*)(q + ((size_t)bh * NS + qrow) * NDH);
#pragma unroll
    for (int i = 0; i < 16; i++) qr[i] = qg[i];

    float4 o4[16];
#pragma unroll
    for (int i = 0; i < 16; i++) o4[i] = make_float4(0.f, 0.f, 0.f, 0.f);
    float m = -1e30f, l = 0.f;
    float* srow = ss + t * 65;

    for (int kt = 0; kt < 16; kt++) {
        __syncthreads();
        const float4* kg = (const float4*)(k + ((size_t)bh * NS + kt * 64) * NDH);
        const float4* vg = (const float4*)(v + ((size_t)bh * NS + kt * 64) * NDH);
#pragma unroll
        for (int i = 0; i < 8; i++) {
            ((float4*)Ks)[t + i * 128] = kg[t + i * 128];
            ((float4*)Vs)[t + i * 128] = vg[t + i * 128];
        }
        __syncthreads();

        float tm = -1e30f;
        for (int j = 0; j < 64; j++) {
            const float4* kr = (const float4*)Ks + j * 16;
            float s = 0.f;
#pragma unroll
            for (int d4 = 0; d4 < 16; d4++) {
                float4 k4 = kr[d4];
                s += qr[d4].x * k4.x + qr[d4].y * k4.y + qr[d4].z * k4.z + qr[d4].w * k4.w;
            }
            s *= 0.125f;   // 1/sqrt(64)
            srow[j] = s;
            tm = fmaxf(tm, s);
        }
        float mn = fmaxf(m, tm);
        float corr = __expf(m - mn);
        l *= corr;
#pragma unroll
        for (int i = 0; i < 16; i++) {
            o4[i].x *= corr; o4[i].y *= corr; o4[i].z *= corr; o4[i].w *= corr;
        }
        float lsum = 0.f;
        for (int j = 0; j < 64; j++) {
            float p = __expf(srow[j] - mn);
            srow[j] = p;
            lsum += p;
        }
        l += lsum;
        m = mn;
        for (int j = 0; j < 64; j++) {
            float p = srow[j];
            const float4* vr = (const float4*)Vs + j * 16;
#pragma unroll
            for (int d4 = 0; d4 < 16; d4++) {
                float4 v4 = vr[d4];
                o4[d4].x += p * v4.x; o4[d4].y += p * v4.y;
                o4[d4].z += p * v4.z; o4[d4].w += p * v4.w;
            }
        }
    }

    float inv = 1.f / l;
    size_t ob = ((size_t)(b * NS + qrow)) * ND + h * NDH;
#pragma unroll
    for (int i = 0; i < 16; i++) {
        float4 xv = *(const float4*)(x + ob + i * 4);
        float4 r4;
        r4.x = xv.x + o4[i].x * inv;
        r4.y = xv.y + o4[i].y * inv;
        r4.z = xv.z + o4[i].z * inv;
        r4.w = xv.w + o4[i].w * inv;
        *(float4*)(out + ob + i * 4) = r4;
    }
}

// ---------------- FFN GEMMs: 128x128 block tile, 8x8 microtile --------------
__device__ __forceinline__ float gelu_exact(float x) {
    return 0.5f * x * (1.0f + erff(x * 0.70710678118654752f));
}

// EPI 0: C = gelu(A@B);  EPI 1: C += A@B (C pre-holds residual)
template <int EPI>
__global__ __launch_bounds__(256) void sgemm_kernel(
    const float* __restrict__ A, const float* __restrict__ Bm,
    float* __restrict__ C, int M, int N, int K)
{
    __shared__ float As[16][128];
    __shared__ float Bs[16][128];
    int t = threadIdx.x;
    int tx = t & 15, ty = t >> 4;
    int row0 = blockIdx.y * 128, col0 = blockIdx.x * 128;
    const float* Ab = A + (size_t)row0 * K;
    const float* Bb = Bm + col0;

    float acc[8][8];
#pragma unroll
    for (int i = 0; i < 8; i++)
#pragma unroll
        for (int j = 0; j < 8; j++) acc[i][j] = 0.f;

    for (int kt = 0; kt < K; kt += 16) {
#pragma unroll
        for (int i = 0; i < 2; i++) {
            int f = t + i * 256;
            int r = f >> 2, c = (f & 3) * 4;
            float4 a4 = *(const float4*)(Ab + (size_t)r * K + kt + c);
            As[c + 0][r] = a4.x; As[c + 1][r] = a4.y;
            As[c + 2][r] = a4.z; As[c + 3][r] = a4.w;
        }
#pragma unroll
        for (int i = 0; i < 2; i++) {
            int f = t + i * 256;
            int r = f >> 5, c = (f & 31) * 4;
            *(float4*)&Bs[r][c] = *(const float4*)(Bb + (size_t)(kt + r) * N + c);
        }
        __syncthreads();
#pragma unroll
        for (int kk = 0; kk < 16; kk++) {
            float a[8], bv[8];
            *(float4*)&a[0]  = *(float4*)&As[kk][ty * 8];
            *(float4*)&a[4]  = *(float4*)&As[kk][ty * 8 + 4];
            *(float4*)&bv[0] = *(float4*)&Bs[kk][tx * 8];
            *(float4*)&bv[4] = *(float4*)&Bs[kk][tx * 8 + 4];
#pragma unroll
            for (int i = 0; i < 8; i++)
#pragma unroll
                for (int j = 0; j < 8; j++) acc[i][j] += a[i] * bv[j];
        }
        __syncthreads();
    }

#pragma unroll
    for (int i = 0; i < 8; i++) {
        int r = row0 + ty * 8 + i;
        float* Cr = C + (size_t)r * N + col0 + tx * 8;
#pragma unroll
        for (int jb = 0; jb < 2; jb++) {
            if (EPI == 0) {
                float4 o;
                o.x = gelu_exact(acc[i][jb * 4 + 0]);
                o.y = gelu_exact(acc[i][jb * 4 + 1]);
                o.z = gelu_exact(acc[i][jb * 4 + 2]);
                o.w = gelu_exact(acc[i][jb * 4 + 3]);
                *(float4*)(Cr + jb * 4) = o;
            } else {
                float4 c4 = *(float4*)(Cr + jb * 4);
                c4.x += acc[i][jb * 4 + 0];
                c4.y += acc[i][jb * 4 + 1];
                c4.z += acc[i][jb * 4 + 2];
                c4.w += acc[i][jb * 4 + 3];
                *(float4*)(Cr + jb * 4) = c4;
            }
        }
    }
}

// ---------------- host launcher ---------------------------------------------
extern "C" void kernel_launch(void* const* d_in, const int* in_sizes, int n_in,
                              void* d_out, int out_size)
{
    const float* x     = (const float*)d_in[0];
    const float* ln1_g = (const float*)d_in[1];
    const float* ln1_b = (const float*)d_in[2];
    const float* Wq    = (const float*)d_in[3];
    const float* bq    = (const float*)d_in[4];
    const float* Wk    = (const float*)d_in[5];
    const float* bk    = (const float*)d_in[6];
    const float* Wv    = (const float*)d_in[7];
    const float* bv    = (const float*)d_in[8];
    const float* ln2_g = (const float*)d_in[9];
    const float* ln2_b = (const float*)d_in[10];
    const float* W1    = (const float*)d_in[11];
    const float* W2    = (const float*)d_in[12];
    float* out = (float*)d_out;

    float *ln1p, *qp, *kp, *vp, *ln2p, *hidp;
    cudaGetSymbolAddress((void**)&ln1p, g_ln1);
    cudaGetSymbolAddress((void**)&qp,   g_q);
    cudaGetSymbolAddress((void**)&kp,   g_k);
    cudaGetSymbolAddress((void**)&vp,   g_v);
    cudaGetSymbolAddress((void**)&ln2p, g_ln2);
    cudaGetSymbolAddress((void**)&hidp, g_hid);

    const int QKV_SMEM  = (12288 + 64 * 68) * 4;           // 66560 B
    const int ATTN_SMEM = (4096 + 4096 + 128 * 65) * 4;    // 66048 B
    cudaFuncSetAttribute(qkv_kernel,  cudaFuncAttributeMaxDynamicSharedMemorySize, QKV_SMEM);
    cudaFuncSetAttribute(attn_kernel, cudaFuncAttributeMaxDynamicSharedMemorySize, ATTN_SMEM);

    // 1. LN1
    ln_kernel<<<NROWS, 256>>>(x, ln1_g, ln1_b, ln1p);
    // 2. per-head QKV projections
    qkv_kernel<<<dim3(NB * NH, NS / 64), 256, QKV_SMEM>>>(ln1p, Wq, bq, Wk, bk, Wv, bv, qp, kp, vp);
    // 3. attention + first residual (writes full d_out = x + msa)
    attn_kernel<<<dim3(NB * NH, NS / 128), 128, ATTN_SMEM>>>(qp, kp, vp, x, out);
    // 4. LN2
    ln_kernel<<<NROWS, 256>>>(out, ln2_g, ln2_b, ln2p);
    // 5. FFN up + GELU
    sgemm_kernel<0><<<dim3(DFF / 128, NROWS / 128), 256>>>(ln2p, W1, hidp, NROWS, DFF, ND);
    // 6. FFN down + second residual (accumulates into d_out)
    sgemm_kernel<1><<<dim3(ND / 128, NROWS / 128), 256>>>(hidp, W2, out, NROWS, ND, DFF);
}

// round 5
// speedup vs baseline: 1.6295x; 1.6295x over previous
#include <cuda_runtime.h>
#include <math.h>
#include <stdint.h>

// Problem constants: B=8, S=1024, D=768, H=12, DH=64
#define NB 8
#define NS 1024
#define ND 768
#define NH 12
#define NDH 64
#define NROWS (NB * NS)          // 8192
#define DFF (4 * ND)             // 3072

// ---------------- scratch (device globals: no allocation allowed) ----------
__device__ float g_ln1[NROWS * ND];
__device__ float g_q[NROWS * ND];
__device__ float g_k[NROWS * ND];
__device__ float g_v[NROWS * ND];
__device__ float g_ln2[NROWS * ND];
__device__ float g_hid[NROWS * DFF];
__device__ float g_w1t[DFF * ND];   // W1^T [3072][768], tf32-rounded
__device__ float g_w2t[ND * DFF];   // W2^T [768][3072], tf32-rounded

// ---------------- helpers ----------------------------------------------------
__device__ __forceinline__ float tf32_rn(float x) {
    uint32_t u;
    asm("cvt.rna.tf32.f32 %0, %1;" : "=r"(u) : "f"(x));
    return __uint_as_float(u);
}
__device__ __forceinline__ void cp_async16(uint32_t s, const void* g) {
    asm volatile("cp.async.cg.shared.global [%0], [%1], 16;" :: "r"(s), "l"(g));
}
__device__ __forceinline__ uint32_t smem_u32(const void* p) {
    uint32_t a;
    asm("{ .reg .u64 t; cvta.to.shared.u64 t, %1; cvt.u32.u64 %0, t; }" : "=r"(a) : "l"(p));
    return a;
}
__device__ __forceinline__ void mma_tf32_16x8x8(
    float& c0, float& c1, float& c2, float& c3,
    uint32_t a0, uint32_t a1, uint32_t a2, uint32_t a3,
    uint32_t b0, uint32_t b1)
{
    asm volatile(
        "mma.sync.aligned.m16n8k8.row.col.f32.tf32.tf32.f32 "
        "{%0,%1,%2,%3}, {%4,%5,%6,%7}, {%8,%9}, {%0,%1,%2,%3};"
        : "+f"(c0), "+f"(c1), "+f"(c2), "+f"(c3)
        : "r"(a0), "r"(a1), "r"(a2), "r"(a3), "r"(b0), "r"(b1));
}
__device__ __forceinline__ float gelu_exact(float x) {
    return 0.5f * x * (1.0f + erff(x * 0.70710678118654752f));
}

// ---------------- LayerNorm (RND=1: round output to tf32) -------------------
template <int RND>
__global__ __launch_bounds__(256) void ln_kernel(
    const float* __restrict__ x, const float* __restrict__ gw,
    const float* __restrict__ bw, float* __restrict__ out)
{
    __shared__ float r1[8], r2[8];
    int row = blockIdx.x, t = threadIdx.x;
    const float* xr = x + (size_t)row * ND;
    float v0 = xr[t], v1 = xr[t + 256], v2 = xr[t + 512];
    float s = v0 + v1 + v2;
#pragma unroll
    for (int o = 16; o > 0; o >>= 1) s += __shfl_xor_sync(0xffffffffu, s, o);
    if ((t & 31) == 0) r1[t >> 5] = s;
    __syncthreads();
    float tot = r1[0] + r1[1] + r1[2] + r1[3] + r1[4] + r1[5] + r1[6] + r1[7];
    float mean = tot * (1.0f / (float)ND);
    float d0 = v0 - mean, d1 = v1 - mean, d2 = v2 - mean;
    float sq = d0 * d0 + d1 * d1 + d2 * d2;
#pragma unroll
    for (int o = 16; o > 0; o >>= 1) sq += __shfl_xor_sync(0xffffffffu, sq, o);
    if ((t & 31) == 0) r2[t >> 5] = sq;
    __syncthreads();
    float var = (r2[0] + r2[1] + r2[2] + r2[3] + r2[4] + r2[5] + r2[6] + r2[7]) * (1.0f / (float)ND);
    float rstd = rsqrtf(var + 1e-5f);
    float* orow = out + (size_t)row * ND;
    float o0 = d0 * rstd * gw[t] + bw[t];
    float o1 = d1 * rstd * gw[t + 256] + bw[t + 256];
    float o2 = d2 * rstd * gw[t + 512] + bw[t + 512];
    if (RND) { o0 = tf32_rn(o0); o1 = tf32_rn(o1); o2 = tf32_rn(o2); }
    orow[t] = o0; orow[t + 256] = o1; orow[t + 512] = o2;
}

// ---------------- transpose + tf32 round: in[R][C] -> out[C][R] -------------
__global__ __launch_bounds__(256) void transpose_tf32(
    const float* __restrict__ in, float* __restrict__ out, int R, int C)
{
    __shared__ float tile[32][33];
    int c0 = blockIdx.x * 32, r0 = blockIdx.y * 32;
    int tx = threadIdx.x & 31, ty = threadIdx.x >> 5;
#pragma unroll
    for (int i = 0; i < 32; i += 8)
        tile[ty + i][tx] = in[(size_t)(r0 + ty + i) * C + c0 + tx];
    __syncthreads();
#pragma unroll
    for (int i = 0; i < 32; i += 8)
        out[(size_t)(c0 + ty + i) * R + r0 + tx] = tf32_rn(tile[tx][ty + i]);
}

// ---------------- QKV: per-head 64x64 projections ---------------------------
__global__ __launch_bounds__(256) void qkv_kernel(
    const float* __restrict__ ln1,
    const float* __restrict__ Wq, const float* __restrict__ bq,
    const float* __restrict__ Wk, const float* __restrict__ bk,
    const float* __restrict__ Wv, const float* __restrict__ bv,
    float* __restrict__ q, float* __restrict__ k, float* __restrict__ v)
{
    extern __shared__ float sm[];
    float* sWq = sm;
    float* sWk = sm + 4096;
    float* sWv = sm + 8192;
    float* xs  = sm + 12288;

    int bh = blockIdx.x;
    int h = bh % NH, b = bh / NH;
    int s0 = blockIdx.y * 64;
    int t = threadIdx.x;

    const float4* wq4 = (const float4*)(Wq + (size_t)h * 4096);
    const float4* wk4 = (const float4*)(Wk + (size_t)h * 4096);
    const float4* wv4 = (const float4*)(Wv + (size_t)h * 4096);
#pragma unroll
    for (int i = 0; i < 4; i++) {
        ((float4*)sWq)[t + i * 256] = wq4[t + i * 256];
        ((float4*)sWk)[t + i * 256] = wk4[t + i * 256];
        ((float4*)sWv)[t + i * 256] = wv4[t + i * 256];
    }
#pragma unroll
    for (int i = 0; i < 4; i++) {
        int f = t + i * 256;
        int r = f >> 4, c = f & 15;
        float4 xv = *(const float4*)(ln1 + ((size_t)(b * NS + s0 + r)) * ND + h * NDH + c * 4);
        *(float4*)(xs + r * 68 + c * 4) = xv;
    }
    __syncthreads();

    int r = t >> 2, ec = (t & 3) * 16;
    float aq[16], ak[16], av[16];
#pragma unroll
    for (int i = 0; i < 16; i++) {
        aq[i] = bq[h * NDH + ec + i];
        ak[i] = bk[h * NDH + ec + i];
        av[i] = bv[h * NDH + ec + i];
    }
    for (int d = 0; d < 64; d++) {
        float xv = xs[r * 68 + d];
#pragma unroll
        for (int i4 = 0; i4 < 4; i4++) {
            float4 wq = *(const float4*)(sWq + d * 64 + ec + i4 * 4);
            float4 wk = *(const float4*)(sWk + d * 64 + ec + i4 * 4);
            float4 wv = *(const float4*)(sWv + d * 64 + ec + i4 * 4);
            aq[i4 * 4 + 0] += xv * wq.x; aq[i4 * 4 + 1] += xv * wq.y;
            aq[i4 * 4 + 2] += xv * wq.z; aq[i4 * 4 + 3] += xv * wq.w;
            ak[i4 * 4 + 0] += xv * wk.x; ak[i4 * 4 + 1] += xv * wk.y;
            ak[i4 * 4 + 2] += xv * wk.z; ak[i4 * 4 + 3] += xv * wk.w;
            av[i4 * 4 + 0] += xv * wv.x; av[i4 * 4 + 1] += xv * wv.y;
            av[i4 * 4 + 2] += xv * wv.z; av[i4 * 4 + 3] += xv * wv.w;
        }
    }
    size_t ob = ((size_t)bh * NS + s0 + r) * NDH + ec;
#pragma unroll
    for (int i4 = 0; i4 < 4; i4++) {
        *(float4*)(q + ob + i4 * 4) = make_float4(aq[i4 * 4], aq[i4 * 4 + 1], aq[i4 * 4 + 2], aq[i4 * 4 + 3]);
        *(float4*)(k + ob + i4 * 4) = make_float4(ak[i4 * 4], ak[i4 * 4 + 1], ak[i4 * 4 + 2], ak[i4 * 4 + 3]);
        *(float4*)(v + ob + i4 * 4) = make_float4(av[i4 * 4], av[i4 * 4 + 1], av[i4 * 4 + 2], av[i4 * 4 + 3]);
    }
}

// ---------------- Attention (flash-style, non-causal) -----------------------
__global__ __launch_bounds__(128) void attn_kernel(
    const float* __restrict__ q, const float* __restrict__ k,
    const float* __restrict__ v, const float* __restrict__ x,
    float* __restrict__ out)
{
    extern __shared__ float sm[];
    float* Ks = sm;
    float* Vs = sm + 4096;
    float* ss = sm + 8192;

    int bh = blockIdx.x;
    int h = bh % NH, b = bh / NH;
    int t = threadIdx.x;
    int qrow = blockIdx.y * 128 + t;

    float4 qr[16];
    const float4* qg = (const float4*)(q + ((size_t)bh * NS + qrow) * NDH);
#pragma unroll
    for (int i = 0; i < 16; i++) qr[i] = qg[i];

    float4 o4[16];
#pragma unroll
    for (int i = 0; i < 16; i++) o4[i] = make_float4(0.f, 0.f, 0.f, 0.f);
    float m = -1e30f, l = 0.f;
    float* srow = ss + t * 65;

    for (int kt = 0; kt < 16; kt++) {
        __syncthreads();
        const float4* kg = (const float4*)(k + ((size_t)bh * NS + kt * 64) * NDH);
        const float4* vg = (const float4*)(v + ((size_t)bh * NS + kt * 64) * NDH);
#pragma unroll
        for (int i = 0; i < 8; i++) {
            ((float4*)Ks)[t + i * 128] = kg[t + i * 128];
            ((float4*)Vs)[t + i * 128] = vg[t + i * 128];
        }
        __syncthreads();

        float tm = -1e30f;
        for (int j = 0; j < 64; j++) {
            const float4* kr = (const float4*)Ks + j * 16;
            float s = 0.f;
#pragma unroll
            for (int d4 = 0; d4 < 16; d4++) {
                float4 k4 = kr[d4];
                s += qr[d4].x * k4.x + qr[d4].y * k4.y + qr[d4].z * k4.z + qr[d4].w * k4.w;
            }
            s *= 0.125f;
            srow[j] = s;
            tm = fmaxf(tm, s);
        }
        float mn = fmaxf(m, tm);
        float corr = __expf(m - mn);
        l *= corr;
#pragma unroll
        for (int i = 0; i < 16; i++) {
            o4[i].x *= corr; o4[i].y *= corr; o4[i].z *= corr; o4[i].w *= corr;
        }
        float lsum = 0.f;
        for (int j = 0; j < 64; j++) {
            float p = __expf(srow[j] - mn);
            srow[j] = p;
            lsum += p;
        }
        l += lsum;
        m = mn;
        for (int j = 0; j < 64; j++) {
            float p = srow[j];
            const float4* vr = (const float4*)Vs + j * 16;
#pragma unroll
            for (int d4 = 0; d4 < 16; d4++) {
                float4 v4 = vr[d4];
                o4[d4].x += p * v4.x; o4[d4].y += p * v4.y;
                o4[d4].z += p * v4.z; o4[d4].w += p * v4.w;
            }
        }
    }

    float inv = 1.f / l;
    size_t ob = ((size_t)(b * NS + qrow)) * ND + h * NDH;
#pragma unroll
    for (int i = 0; i < 16; i++) {
        float4 xv = *(const float4*)(x + ob + i * 4);
        float4 r4;
        r4.x = xv.x + o4[i].x * inv;
        r4.y = xv.y + o4[i].y * inv;
        r4.z = xv.z + o4[i].z * inv;
        r4.w = xv.w + o4[i].w * inv;
        *(float4*)(out + ob + i * 4) = r4;
    }
}

// ---------------- tf32 mma.sync GEMM ----------------------------------------
// C[8192][N] = A[8192][K] @ Bt[N][K]^T.  Block 128x128, K-tile 32.
// 8 warps, warp grid 2(m) x 4(n), warp tile 64x32.
// Double-buffered cp.async. Smem rows padded to 36 floats (conflict-free frags).
// EPI 0: C = tf32_rn(gelu(acc)); EPI 1: C += acc.
#define GS 36                         // smem row stride (floats)
#define BUF (128 * GS)                // one matrix buffer (floats)
#define GEMM_SMEM_BYTES (4 * BUF * 4) // A0,B0,A1,B1 = 73728 B

template <int EPI>
__global__ __launch_bounds__(256) void gemm_mma(
    const float* __restrict__ A, const float* __restrict__ Bt,
    float* __restrict__ C, int K, int N)
{
    extern __shared__ float smf[];
    // layout: [A0][B0][A1][B1], each 128*GS floats
    uint32_t sbase = smem_u32(smf);

    int t = threadIdx.x;
    int w = t >> 5, lane = t & 31;
    int gid = lane >> 2, tig = lane & 3;
    int wm = w >> 2, wn = w & 3;           // 2 x 4 warp grid
    int m0 = blockIdx.y * 128, n0 = blockIdx.x * 128;

    // loader mapping: 4 float4 per matrix per thread
    int lr = t >> 1;                       // 0..127 : two threads per row
    int lc4 = (t & 1) * 4;                 // float4 index in row (0 or 4)
    const float* Ag = A + (size_t)(m0 + lr) * K + lc4 * 4;
    const float* Bg = Bt + (size_t)(n0 + lr) * K + lc4 * 4;
    uint32_t sA = sbase + (uint32_t)(lr * GS + lc4 * 4) * 4;
    uint32_t sB = sA + BUF * 4;

    float acc[4][4][4];
#pragma unroll
    for (int i = 0; i < 4; i++)
#pragma unroll
        for (int j = 0; j < 4; j++)
#pragma unroll
            for (int r = 0; r < 4; r++) acc[i][j][r] = 0.f;

    int nkt = K >> 5;
    // prefetch tile 0
    {
#pragma unroll
        for (int i = 0; i < 4; i++) {
            cp_async16(sA + i * 16, Ag + i * 4);
            cp_async16(sB + i * 16, Bg + i * 4);
        }
        asm volatile("cp.async.commit_group;" ::: "memory");
    }

    const float* As_all = smf;
    for (int kt = 0; kt < nkt; kt++) {
        int cur = kt & 1;
        if (kt + 1 < nkt) {
            int nxt = (kt + 1) & 1;
            const float* Agn = Ag + (kt + 1) * 32;
            const float* Bgn = Bg + (kt + 1) * 32;
            uint32_t dA = sA + (uint32_t)(nxt * 2 * BUF) * 4;
            uint32_t dB = sB + (uint32_t)(nxt * 2 * BUF) * 4;
#pragma unroll
            for (int i = 0; i < 4; i++) {
                cp_async16(dA + i * 16, Agn + i * 4);
                cp_async16(dB + i * 16, Bgn + i * 4);
            }
            asm volatile("cp.async.commit_group;" ::: "memory");
            asm volatile("cp.async.wait_group 1;" ::: "memory");
        } else {
            asm volatile("cp.async.wait_group 0;" ::: "memory");
        }
        __syncthreads();

        const float* As = As_all + cur * 2 * BUF;
        const float* Bs = As + BUF;
        const uint32_t* Au = (const uint32_t*)As;
        const uint32_t* Bu = (const uint32_t*)Bs;

#pragma unroll
        for (int ks = 0; ks < 4; ks++) {
            uint32_t a[4][4];
#pragma unroll
            for (int mf = 0; mf < 4; mf++) {
                int ar = (wm * 64 + mf * 16 + gid) * GS + ks * 8 + tig;
                a[mf][0] = Au[ar];
                a[mf][1] = Au[ar + 8 * GS];
                a[mf][2] = Au[ar + 4];
                a[mf][3] = Au[ar + 8 * GS + 4];
            }
            uint32_t bgs[4][2];
#pragma unroll
            for (int nf = 0; nf < 4; nf++) {
                int br = (wn * 32 + nf * 8 + gid) * GS + ks * 8 + tig;
                bgs[nf][0] = Bu[br];
                bgs[nf][1] = Bu[br + 4];
            }
#pragma unroll
            for (int mf = 0; mf < 4; mf++)
#pragma unroll
                for (int nf = 0; nf < 4; nf++)
                    mma_tf32_16x8x8(acc[mf][nf][0], acc[mf][nf][1],
                                    acc[mf][nf][2], acc[mf][nf][3],
                                    a[mf][0], a[mf][1], a[mf][2], a[mf][3],
                                    bgs[nf][0], bgs[nf][1]);
        }
        __syncthreads();
    }

    // epilogue: direct float2 stores (full 32B sector coverage per 4 lanes)
#pragma unroll
    for (int mf = 0; mf < 4; mf++) {
#pragma unroll
        for (int nf = 0; nf < 4; nf++) {
            int row = m0 + wm * 64 + mf * 16 + gid;
            int col = n0 + wn * 32 + nf * 8 + tig * 2;
            float* p0 = C + (size_t)row * N + col;
            float* p1 = C + (size_t)(row + 8) * N + col;
            float2 v0 = make_float2(acc[mf][nf][0], acc[mf][nf][1]);
            float2 v1 = make_float2(acc[mf][nf][2], acc[mf][nf][3]);
            if (EPI == 0) {
                v0.x = tf32_rn(gelu_exact(v0.x)); v0.y = tf32_rn(gelu_exact(v0.y));
                v1.x = tf32_rn(gelu_exact(v1.x)); v1.y = tf32_rn(gelu_exact(v1.y));
            } else {
                float2 c0 = *(float2*)p0, c1 = *(float2*)p1;
                v0.x += c0.x; v0.y += c0.y;
                v1.x += c1.x; v1.y += c1.y;
            }
            *(float2*)p0 = v0;
            *(float2*)p1 = v1;
        }
    }
}

// ---------------- host launcher ---------------------------------------------
extern "C" void kernel_launch(void* const* d_in, const int* in_sizes, int n_in,
                              void* d_out, int out_size)
{
    const float* x     = (const float*)d_in[0];
    const float* ln1_g = (const float*)d_in[1];
    const float* ln1_b = (const float*)d_in[2];
    const float* Wq    = (const float*)d_in[3];
    const float* bq    = (const float*)d_in[4];
    const float* Wk    = (const float*)d_in[5];
    const float* bk    = (const float*)d_in[6];
    const float* Wv    = (const float*)d_in[7];
    const float* bv    = (const float*)d_in[8];
    const float* ln2_g = (const float*)d_in[9];
    const float* ln2_b = (const float*)d_in[10];
    const float* W1    = (const float*)d_in[11];
    const float* W2    = (const float*)d_in[12];
    float* out = (float*)d_out;

    float *ln1p, *qp, *kp, *vp, *ln2p, *hidp, *w1tp, *w2tp;
    cudaGetSymbolAddress((void**)&ln1p, g_ln1);
    cudaGetSymbolAddress((void**)&qp,   g_q);
    cudaGetSymbolAddress((void**)&kp,   g_k);
    cudaGetSymbolAddress((void**)&vp,   g_v);
    cudaGetSymbolAddress((void**)&ln2p, g_ln2);
    cudaGetSymbolAddress((void**)&hidp, g_hid);
    cudaGetSymbolAddress((void**)&w1tp, g_w1t);
    cudaGetSymbolAddress((void**)&w2tp, g_w2t);

    const int QKV_SMEM  = (12288 + 64 * 68) * 4;
    const int ATTN_SMEM = (4096 + 4096 + 128 * 65) * 4;
    cudaFuncSetAttribute(qkv_kernel,  cudaFuncAttributeMaxDynamicSharedMemorySize, QKV_SMEM);
    cudaFuncSetAttribute(attn_kernel, cudaFuncAttributeMaxDynamicSharedMemorySize, ATTN_SMEM);
    cudaFuncSetAttribute(gemm_mma<0>, cudaFuncAttributeMaxDynamicSharedMemorySize, GEMM_SMEM_BYTES);
    cudaFuncSetAttribute(gemm_mma<1>, cudaFuncAttributeMaxDynamicSharedMemorySize, GEMM_SMEM_BYTES);

    // 0/1: weight transposes (+ tf32 rounding)
    transpose_tf32<<<dim3(DFF / 32, ND / 32), 256>>>(W1, w1tp, ND, DFF);   // -> [3072][768]
    transpose_tf32<<<dim3(ND / 32, DFF / 32), 256>>>(W2, w2tp, DFF, ND);   // -> [768][3072]
    // 2: LN1
    ln_kernel<0><<<NROWS, 256>>>(x, ln1_g, ln1_b, ln1p);
    // 3: per-head QKV projections
    qkv_kernel<<<dim3(NB * NH, NS / 64), 256, QKV_SMEM>>>(ln1p, Wq, bq, Wk, bk, Wv, bv, qp, kp, vp);
    // 4: attention + first residual (d_out = x + msa)
    attn_kernel<<<dim3(NB * NH, NS / 128), 128, ATTN_SMEM>>>(qp, kp, vp, x, out);
    // 5: LN2 (tf32-rounded, feeds tensor GEMM)
    ln_kernel<1><<<NROWS, 256>>>(out, ln2_g, ln2_b, ln2p);
    // 6: FFN up + GELU (mma.sync tf32)
    gemm_mma<0><<<dim3(DFF / 128, NROWS / 128), 256, GEMM_SMEM_BYTES>>>(ln2p, w1tp, hidp, ND, DFF);
    // 7: FFN down + second residual (mma.sync tf32)
    gemm_mma<1><<<dim3(ND / 128, NROWS / 128), 256, GEMM_SMEM_BYTES>>>(hidp, w2tp, out, DFF, ND);
}

// round 6
// speedup vs baseline: 1.6770x; 1.0291x over previous
#include <cuda_runtime.h>
#include <math.h>
#include <stdint.h>

// Problem constants: B=8, S=1024, D=768, H=12, DH=64
#define NB 8
#define NS 1024
#define ND 768
#define NH 12
#define NDH 64
#define NROWS (NB * NS)          // 8192
#define DFF (4 * ND)             // 3072

// ---------------- scratch (device globals: no allocation allowed) ----------
__device__ float g_ln1[NROWS * ND];
__device__ float g_q[NROWS * ND];
__device__ float g_k[NROWS * ND];
__device__ float g_v[NROWS * ND];
__device__ float g_ln2[NROWS * ND];
__device__ float g_hid[NROWS * DFF];
__device__ float g_w1t[DFF * ND];   // W1^T [3072][768], tf32-rounded
__device__ float g_w2t[ND * DFF];   // W2^T [768][3072], tf32-rounded

// ---------------- helpers ----------------------------------------------------
__device__ __forceinline__ float tf32_rn(float x) {
    uint32_t u;
    asm("cvt.rna.tf32.f32 %0, %1;" : "=r"(u) : "f"(x));
    return __uint_as_float(u);
}
__device__ __forceinline__ void cp_async16(uint32_t s, const void* g) {
    asm volatile("cp.async.cg.shared.global [%0], [%1], 16;" :: "r"(s), "l"(g));
}
__device__ __forceinline__ uint32_t smem_u32(const void* p) {
    uint32_t a;
    asm("{ .reg .u64 t; cvta.to.shared.u64 t, %1; cvt.u32.u64 %0, t; }" : "=r"(a) : "l"(p));
    return a;
}
__device__ __forceinline__ void mma_tf32_16x8x8(
    float& c0, float& c1, float& c2, float& c3,
    uint32_t a0, uint32_t a1, uint32_t a2, uint32_t a3,
    uint32_t b0, uint32_t b1)
{
    asm volatile(
        "mma.sync.aligned.m16n8k8.row.col.f32.tf32.tf32.f32 "
        "{%0,%1,%2,%3}, {%4,%5,%6,%7}, {%8,%9}, {%0,%1,%2,%3};"
        : "+f"(c0), "+f"(c1), "+f"(c2), "+f"(c3)
        : "r"(a0), "r"(a1), "r"(a2), "r"(a3), "r"(b0), "r"(b1));
}
__device__ __forceinline__ float gelu_exact(float x) {
    return 0.5f * x * (1.0f + erff(x * 0.70710678118654752f));
}

// ---------------- LayerNorm (RND=1: round output to tf32) -------------------
template <int RND>
__global__ __launch_bounds__(256) void ln_kernel(
    const float* __restrict__ x, const float* __restrict__ gw,
    const float* __restrict__ bw, float* __restrict__ out)
{
    __shared__ float r1[8], r2[8];
    int row = blockIdx.x, t = threadIdx.x;
    const float* xr = x + (size_t)row * ND;
    float v0 = xr[t], v1 = xr[t + 256], v2 = xr[t + 512];
    float s = v0 + v1 + v2;
#pragma unroll
    for (int o = 16; o > 0; o >>= 1) s += __shfl_xor_sync(0xffffffffu, s, o);
    if ((t & 31) == 0) r1[t >> 5] = s;
    __syncthreads();
    float tot = r1[0] + r1[1] + r1[2] + r1[3] + r1[4] + r1[5] + r1[6] + r1[7];
    float mean = tot * (1.0f / (float)ND);
    float d0 = v0 - mean, d1 = v1 - mean, d2 = v2 - mean;
    float sq = d0 * d0 + d1 * d1 + d2 * d2;
#pragma unroll
    for (int o = 16; o > 0; o >>= 1) sq += __shfl_xor_sync(0xffffffffu, sq, o);
    if ((t & 31) == 0) r2[t >> 5] = sq;
    __syncthreads();
    float var = (r2[0] + r2[1] + r2[2] + r2[3] + r2[4] + r2[5] + r2[6] + r2[7]) * (1.0f / (float)ND);
    float rstd = rsqrtf(var + 1e-5f);
    float* orow = out + (size_t)row * ND;
    float o0 = d0 * rstd * gw[t] + bw[t];
    float o1 = d1 * rstd * gw[t + 256] + bw[t + 256];
    float o2 = d2 * rstd * gw[t + 512] + bw[t + 512];
    if (RND) { o0 = tf32_rn(o0); o1 = tf32_rn(o1); o2 = tf32_rn(o2); }
    orow[t] = o0; orow[t + 256] = o1; orow[t + 512] = o2;
}

// ---------------- transpose + tf32 round: in[R][C] -> out[C][R] -------------
__global__ __launch_bounds__(256) void transpose_tf32(
    const float* __restrict__ in, float* __restrict__ out, int R, int C)
{
    __shared__ float tile[32][33];
    int c0 = blockIdx.x * 32, r0 = blockIdx.y * 32;
    int tx = threadIdx.x & 31, ty = threadIdx.x >> 5;
#pragma unroll
    for (int i = 0; i < 32; i += 8)
        tile[ty + i][tx] = in[(size_t)(r0 + ty + i) * C + c0 + tx];
    __syncthreads();
#pragma unroll
    for (int i = 0; i < 32; i += 8)
        out[(size_t)(c0 + ty + i) * R + r0 + tx] = tf32_rn(tile[tx][ty + i]);
}

// ---------------- QKV: per-head 64x64 projections (tf32-rounded outputs) ----
__global__ __launch_bounds__(256) void qkv_kernel(
    const float* __restrict__ ln1,
    const float* __restrict__ Wq, const float* __restrict__ bq,
    const float* __restrict__ Wk, const float* __restrict__ bk,
    const float* __restrict__ Wv, const float* __restrict__ bv,
    float* __restrict__ q, float* __restrict__ k, float* __restrict__ v)
{
    extern __shared__ float sm[];
    float* sWq = sm;
    float* sWk = sm + 4096;
    float* sWv = sm + 8192;
    float* xs  = sm + 12288;

    int bh = blockIdx.x;
    int h = bh % NH, b = bh / NH;
    int s0 = blockIdx.y * 64;
    int t = threadIdx.x;

    const float4* wq4 = (const float4*)(Wq + (size_t)h * 4096);
    const float4* wk4 = (const float4*)(Wk + (size_t)h * 4096);
    const float4* wv4 = (const float4*)(Wv + (size_t)h * 4096);
#pragma unroll
    for (int i = 0; i < 4; i++) {
        ((float4*)sWq)[t + i * 256] = wq4[t + i * 256];
        ((float4*)sWk)[t + i * 256] = wk4[t + i * 256];
        ((float4*)sWv)[t + i * 256] = wv4[t + i * 256];
    }
#pragma unroll
    for (int i = 0; i < 4; i++) {
        int f = t + i * 256;
        int r = f >> 4, c = f & 15;
        float4 xv = *(const float4*)(ln1 + ((size_t)(b * NS + s0 + r)) * ND + h * NDH + c * 4);
        *(float4*)(xs + r * 68 + c * 4) = xv;
    }
    __syncthreads();

    int r = t >> 2, ec = (t & 3) * 16;
    float aq[16], ak[16], av[16];
#pragma unroll
    for (int i = 0; i < 16; i++) {
        aq[i] = bq[h * NDH + ec + i];
        ak[i] = bk[h * NDH + ec + i];
        av[i] = bv[h * NDH + ec + i];
    }
    for (int d = 0; d < 64; d++) {
        float xv = xs[r * 68 + d];
#pragma unroll
        for (int i4 = 0; i4 < 4; i4++) {
            float4 wq = *(const float4*)(sWq + d * 64 + ec + i4 * 4);
            float4 wk = *(const float4*)(sWk + d * 64 + ec + i4 * 4);
            float4 wv = *(const float4*)(sWv + d * 64 + ec + i4 * 4);
            aq[i4 * 4 + 0] += xv * wq.x; aq[i4 * 4 + 1] += xv * wq.y;
            aq[i4 * 4 + 2] += xv * wq.z; aq[i4 * 4 + 3] += xv * wq.w;
            ak[i4 * 4 + 0] += xv * wk.x; ak[i4 * 4 + 1] += xv * wk.y;
            ak[i4 * 4 + 2] += xv * wk.z; ak[i4 * 4 + 3] += xv * wk.w;
            av[i4 * 4 + 0] += xv * wv.x; av[i4 * 4 + 1] += xv * wv.y;
            av[i4 * 4 + 2] += xv * wv.z; av[i4 * 4 + 3] += xv * wv.w;
        }
    }
    size_t ob = ((size_t)bh * NS + s0 + r) * NDH + ec;
#pragma unroll
    for (int i4 = 0; i4 < 4; i4++) {
        *(float4*)(q + ob + i4 * 4) = make_float4(tf32_rn(aq[i4 * 4]), tf32_rn(aq[i4 * 4 + 1]),
                                                 tf32_rn(aq[i4 * 4 + 2]), tf32_rn(aq[i4 * 4 + 3]));
        *(float4*)(k + ob + i4 * 4) = make_float4(tf32_rn(ak[i4 * 4]), tf32_rn(ak[i4 * 4 + 1]),
                                                 tf32_rn(ak[i4 * 4 + 2]), tf32_rn(ak[i4 * 4 + 3]));
        *(float4*)(v + ob + i4 * 4) = make_float4(tf32_rn(av[i4 * 4]), tf32_rn(av[i4 * 4 + 1]),
                                                 tf32_rn(av[i4 * 4 + 2]), tf32_rn(av[i4 * 4 + 3]));
    }
}

// ---------------- Attention: tf32 mma.sync flash attention ------------------
// CTA: 128 q-rows, 8 warps (16 rows each), k-tiles of 64 keys.
// Q in register A-frags (scaled 1/8). K smem stride 68 (n-major frag reads
// conflict-free: bank=gid*4+tig). V smem stride 72 (k-major frag reads
// conflict-free: bank=tig*8+gid). P staged in warp-private smem stride 68.
#define KS_STR 68
#define VS_STR 72
#define PS_STR 68
#define ATTN_SMEM_BYTES ((64 * KS_STR + 64 * VS_STR + 128 * PS_STR) * 4)  // 70656

__global__ __launch_bounds__(256, 2) void attn_mma_kernel(
    const float* __restrict__ q, const float* __restrict__ k,
    const float* __restrict__ v, const float* __restrict__ x,
    float* __restrict__ out)
{
    extern __shared__ float sm[];
    float* Ks = sm;                        // [64][KS_STR]
    float* Vs = sm + 64 * KS_STR;          // [64][VS_STR]
    float* Ps = sm + 64 * KS_STR + 64 * VS_STR;  // [128][PS_STR]

    int bh = blockIdx.x;
    int h = bh % NH, b = bh / NH;
    int t = threadIdx.x;
    int w = t >> 5, lane = t & 31;
    int gid = lane >> 2, tig = lane & 3;
    int qbase = blockIdx.y * 128;
    int wrow = w * 16;

    // Q fragments (x 1/8, exact on tf32 values)
    uint32_t qf[8][4];
    {
        const float* Qg = q + ((size_t)bh * NS + qbase + wrow) * NDH;
#pragma unroll
        for (int kc = 0; kc < 8; kc++) {
            qf[kc][0] = __float_as_uint(Qg[gid * NDH + kc * 8 + tig] * 0.125f);
            qf[kc][1] = __float_as_uint(Qg[(gid + 8) * NDH + kc * 8 + tig] * 0.125f);
            qf[kc][2] = __float_as_uint(Qg[gid * NDH + kc * 8 + tig + 4] * 0.125f);
            qf[kc][3] = __float_as_uint(Qg[(gid + 8) * NDH + kc * 8 + tig + 4] * 0.125f);
        }
    }

    float oa[8][4];
#pragma unroll
    for (int nf = 0; nf < 8; nf++) { oa[nf][0] = oa[nf][1] = oa[nf][2] = oa[nf][3] = 0.f; }
    float m0 = -1e30f, m1 = -1e30f, l0 = 0.f, l1 = 0.f;

    const uint32_t* Ku = (const uint32_t*)Ks;
    const uint32_t* Vu = (const uint32_t*)Vs;
    const uint32_t* Pu = (const uint32_t*)Ps;

    for (int kt = 0; kt < 16; kt++) {
        __syncthreads();
        const float* Kg = k + ((size_t)bh * NS + kt * 64) * NDH;
        const float* Vg = v + ((size_t)bh * NS + kt * 64) * NDH;
#pragma unroll
        for (int i = 0; i < 4; i++) {
            int fi = t + i * 256;
            int row = fi >> 4, c4 = (fi & 15) * 4;
            *(float4*)(Ks + row * KS_STR + c4) = *(const float4*)(Kg + row * NDH + c4);
            *(float4*)(Vs + row * VS_STR + c4) = *(const float4*)(Vg + row * NDH + c4);
        }
        __syncthreads();

        // S = (Q/8) K^T
        float sa[8][4];
#pragma unroll
        for (int nf = 0; nf < 8; nf++) { sa[nf][0] = sa[nf][1] = sa[nf][2] = sa[nf][3] = 0.f; }
#pragma unroll
        for (int kc = 0; kc < 8; kc++) {
#pragma unroll
            for (int nf = 0; nf < 8; nf++) {
                uint32_t b0 = Ku[(nf * 8 + gid) * KS_STR + kc * 8 + tig];
                uint32_t b1 = Ku[(nf * 8 + gid) * KS_STR + kc * 8 + tig + 4];
                mma_tf32_16x8x8(sa[nf][0], sa[nf][1], sa[nf][2], sa[nf][3],
                                qf[kc][0], qf[kc][1], qf[kc][2], qf[kc][3], b0, b1);
            }
        }

        // online softmax
        float tm0 = -1e30f, tm1 = -1e30f;
#pragma unroll
        for (int nf = 0; nf < 8; nf++) {
            tm0 = fmaxf(tm0, fmaxf(sa[nf][0], sa[nf][1]));
            tm1 = fmaxf(tm1, fmaxf(sa[nf][2], sa[nf][3]));
        }
        tm0 = fmaxf(tm0, __shfl_xor_sync(0xffffffffu, tm0, 1));
        tm0 = fmaxf(tm0, __shfl_xor_sync(0xffffffffu, tm0, 2));
        tm1 = fmaxf(tm1, __shfl_xor_sync(0xffffffffu, tm1, 1));
        tm1 = fmaxf(tm1, __shfl_xor_sync(0xffffffffu, tm1, 2));
        float mn0 = fmaxf(m0, tm0), mn1 = fmaxf(m1, tm1);
        float c0 = __expf(m0 - mn0), c1 = __expf(m1 - mn1);
        m0 = mn0; m1 = mn1;

        float ls0 = 0.f, ls1 = 0.f;
        float* Pr0 = Ps + (wrow + gid) * PS_STR + 2 * tig;
        float* Pr1 = Ps + (wrow + gid + 8) * PS_STR + 2 * tig;
#pragma unroll
        for (int nf = 0; nf < 8; nf++) {
            float p00 = __expf(sa[nf][0] - mn0);
            float p01 = __expf(sa[nf][1] - mn0);
            float p10 = __expf(sa[nf][2] - mn1);
            float p11 = __expf(sa[nf][3] - mn1);
            ls0 += p00 + p01;
            ls1 += p10 + p11;
            *(float2*)(Pr0 + nf * 8) = make_float2(tf32_rn(p00), tf32_rn(p01));
            *(float2*)(Pr1 + nf * 8) = make_float2(tf32_rn(p10), tf32_rn(p11));
        }
        ls0 += __shfl_xor_sync(0xffffffffu, ls0, 1);
        ls0 += __shfl_xor_sync(0xffffffffu, ls0, 2);
        ls1 += __shfl_xor_sync(0xffffffffu, ls1, 1);
        ls1 += __shfl_xor_sync(0xffffffffu, ls1, 2);
        l0 = l0 * c0 + ls0;
        l1 = l1 * c1 + ls1;
#pragma unroll
        for (int nf = 0; nf < 8; nf++) {
            oa[nf][0] *= c0; oa[nf][1] *= c0;
            oa[nf][2] *= c1; oa[nf][3] *= c1;
        }
        __syncwarp();

        // O += P V
#pragma unroll
        for (int kc = 0; kc < 8; kc++) {
            uint32_t a0 = Pu[(wrow + gid) * PS_STR + kc * 8 + tig];
            uint32_t a1 = Pu[(wrow + gid + 8) * PS_STR + kc * 8 + tig];
            uint32_t a2 = Pu[(wrow + gid) * PS_STR + kc * 8 + tig + 4];
            uint32_t a3 = Pu[(wrow + gid + 8) * PS_STR + kc * 8 + tig + 4];
#pragma unroll
            for (int nf = 0; nf < 8; nf++) {
                uint32_t b0 = Vu[(kc * 8 + tig) * VS_STR + nf * 8 + gid];
                uint32_t b1 = Vu[(kc * 8 + tig + 4) * VS_STR + nf * 8 + gid];
                mma_tf32_16x8x8(oa[nf][0], oa[nf][1], oa[nf][2], oa[nf][3],
                                a0, a1, a2, a3, b0, b1);
            }
        }
        __syncwarp();
    }

    // epilogue: normalize + residual
    float inv0 = 1.f / l0, inv1 = 1.f / l1;
    int r0 = qbase + wrow + gid;
    size_t o0 = ((size_t)(b * NS) + r0) * ND + h * NDH;
    size_t o1 = o0 + (size_t)8 * ND;
#pragma unroll
    for (int nf = 0; nf < 8; nf++) {
        int col = nf * 8 + 2 * tig;
        float2 x0 = *(const float2*)(x + o0 + col);
        float2 x1 = *(const float2*)(x + o1 + col);
        *(float2*)(out + o0 + col) = make_float2(x0.x + oa[nf][0] * inv0, x0.y + oa[nf][1] * inv0);
        *(float2*)(out + o1 + col) = make_float2(x1.x + oa[nf][2] * inv1, x1.y + oa[nf][3] * inv1);
    }
}

// ---------------- tf32 mma.sync GEMM (FFN) ----------------------------------
#define GS 36
#define BUF (128 * GS)
#define GEMM_SMEM_BYTES (4 * BUF * 4)

template <int EPI>
__global__ __launch_bounds__(256) void gemm_mma(
    const float* __restrict__ A, const float* __restrict__ Bt,
    float* __restrict__ C, int K, int N)
{
    extern __shared__ float smf[];
    uint32_t sbase = smem_u32(smf);

    int t = threadIdx.x;
    int w = t >> 5, lane = t & 31;
    int gid = lane >> 2, tig = lane & 3;
    int wm = w >> 2, wn = w & 3;
    int m0 = blockIdx.y * 128, n0 = blockIdx.x * 128;

    int lr = t >> 1;
    int lc4 = (t & 1) * 4;
    const float* Ag = A + (size_t)(m0 + lr) * K + lc4 * 4;
    const float* Bg = Bt + (size_t)(n0 + lr) * K + lc4 * 4;
    uint32_t sA = sbase + (uint32_t)(lr * GS + lc4 * 4) * 4;
    uint32_t sB = sA + BUF * 4;

    float acc[4][4][4];
#pragma unroll
    for (int i = 0; i < 4; i++)
#pragma unroll
        for (int j = 0; j < 4; j++)
#pragma unroll
            for (int r = 0; r < 4; r++) acc[i][j][r] = 0.f;

    int nkt = K >> 5;
    {
#pragma unroll
        for (int i = 0; i < 4; i++) {
            cp_async16(sA + i * 16, Ag + i * 4);
            cp_async16(sB + i * 16, Bg + i * 4);
        }
        asm volatile("cp.async.commit_group;" ::: "memory");
    }

    const float* As_all = smf;
    for (int kt = 0; kt < nkt; kt++) {
        int cur = kt & 1;
        if (kt + 1 < nkt) {
            int nxt = (kt + 1) & 1;
            const float* Agn = Ag + (kt + 1) * 32;
            const float* Bgn = Bg + (kt + 1) * 32;
            uint32_t dA = sA + (uint32_t)(nxt * 2 * BUF) * 4;
            uint32_t dB = sB + (uint32_t)(nxt * 2 * BUF) * 4;
#pragma unroll
            for (int i = 0; i < 4; i++) {
                cp_async16(dA + i * 16, Agn + i * 4);
                cp_async16(dB + i * 16, Bgn + i * 4);
            }
            asm volatile("cp.async.commit_group;" ::: "memory");
            asm volatile("cp.async.wait_group 1;" ::: "memory");
        } else {
            asm volatile("cp.async.wait_group 0;" ::: "memory");
        }
        __syncthreads();

        const float* As = As_all + cur * 2 * BUF;
        const float* Bs = As + BUF;
        const uint32_t* Au = (const uint32_t*)As;
        const uint32_t* Bu = (const uint32_t*)Bs;

#pragma unroll
        for (int ks = 0; ks < 4; ks++) {
            uint32_t a[4][4];
#pragma unroll
            for (int mf = 0; mf < 4; mf++) {
                int ar = (wm * 64 + mf * 16 + gid) * GS + ks * 8 + tig;
                a[mf][0] = Au[ar];
                a[mf][1] = Au[ar + 8 * GS];
                a[mf][2] = Au[ar + 4];
                a[mf][3] = Au[ar + 8 * GS + 4];
            }
            uint32_t bgs[4][2];
#pragma unroll
            for (int nf = 0; nf < 4; nf++) {
                int br = (wn * 32 + nf * 8 + gid) * GS + ks * 8 + tig;
                bgs[nf][0] = Bu[br];
                bgs[nf][1] = Bu[br + 4];
            }
#pragma unroll
            for (int mf = 0; mf < 4; mf++)
#pragma unroll
                for (int nf = 0; nf < 4; nf++)
                    mma_tf32_16x8x8(acc[mf][nf][0], acc[mf][nf][1],
                                    acc[mf][nf][2], acc[mf][nf][3],
                                    a[mf][0], a[mf][1], a[mf][2], a[mf][3],
                                    bgs[nf][0], bgs[nf][1]);
        }
        __syncthreads();
    }

#pragma unroll
    for (int mf = 0; mf < 4; mf++) {
#pragma unroll
        for (int nf = 0; nf < 4; nf++) {
            int row = m0 + wm * 64 + mf * 16 + gid;
            int col = n0 + wn * 32 + nf * 8 + tig * 2;
            float* p0 = C + (size_t)row * N + col;
            float* p1 = C + (size_t)(row + 8) * N + col;
            float2 v0 = make_float2(acc[mf][nf][0], acc[mf][nf][1]);
            float2 v1 = make_float2(acc[mf][nf][2], acc[mf][nf][3]);
            if (EPI == 0) {
                v0.x = tf32_rn(gelu_exact(v0.x)); v0.y = tf32_rn(gelu_exact(v0.y));
                v1.x = tf32_rn(gelu_exact(v1.x)); v1.y = tf32_rn(gelu_exact(v1.y));
            } else {
                float2 c0 = *(float2*)p0, c1 = *(float2*)p1;
                v0.x += c0.x; v0.y += c0.y;
                v1.x += c1.x; v1.y += c1.y;
            }
            *(float2*)p0 = v0;
            *(float2*)p1 = v1;
        }
    }
}

// ---------------- host launcher ---------------------------------------------
extern "C" void kernel_launch(void* const* d_in, const int* in_sizes, int n_in,
                              void* d_out, int out_size)
{
    const float* x     = (const float*)d_in[0];
    const float* ln1_g = (const float*)d_in[1];
    const float* ln1_b = (const float*)d_in[2];
    const float* Wq    = (const float*)d_in[3];
    const float* bq    = (const float*)d_in[4];
    const float* Wk    = (const float*)d_in[5];
    const float* bk    = (const float*)d_in[6];
    const float* Wv    = (const float*)d_in[7];
    const float* bv    = (const float*)d_in[8];
    const float* ln2_g = (const float*)d_in[9];
    const float* ln2_b = (const float*)d_in[10];
    const float* W1    = (const float*)d_in[11];
    const float* W2    = (const float*)d_in[12];
    float* out = (float*)d_out;

    float *ln1p, *qp, *kp, *vp, *ln2p, *hidp, *w1tp, *w2tp;
    cudaGetSymbolAddress((void**)&ln1p, g_ln1);
    cudaGetSymbolAddress((void**)&qp,   g_q);
    cudaGetSymbolAddress((void**)&kp,   g_k);
    cudaGetSymbolAddress((void**)&vp,   g_v);
    cudaGetSymbolAddress((void**)&ln2p, g_ln2);
    cudaGetSymbolAddress((void**)&hidp, g_hid);
    cudaGetSymbolAddress((void**)&w1tp, g_w1t);
    cudaGetSymbolAddress((void**)&w2tp, g_w2t);

    const int QKV_SMEM = (12288 + 64 * 68) * 4;
    cudaFuncSetAttribute(qkv_kernel, cudaFuncAttributeMaxDynamicSharedMemorySize, QKV_SMEM);
    cudaFuncSetAttribute(attn_mma_kernel, cudaFuncAttributeMaxDynamicSharedMemorySize, ATTN_SMEM_BYTES);
    cudaFuncSetAttribute(gemm_mma<0>, cudaFuncAttributeMaxDynamicSharedMemorySize, GEMM_SMEM_BYTES);
    cudaFuncSetAttribute(gemm_mma<1>, cudaFuncAttributeMaxDynamicSharedMemorySize, GEMM_SMEM_BYTES);

    // 0/1: weight transposes (+ tf32 rounding)
    transpose_tf32<<<dim3(DFF / 32, ND / 32), 256>>>(W1, w1tp, ND, DFF);
    transpose_tf32<<<dim3(ND / 32, DFF / 32), 256>>>(W2, w2tp, DFF, ND);
    // 2: LN1
    ln_kernel<0><<<NROWS, 256>>>(x, ln1_g, ln1_b, ln1p);
    // 3: per-head QKV projections (tf32-rounded outputs)
    qkv_kernel<<<dim3(NB * NH, NS / 64), 256, QKV_SMEM>>>(ln1p, Wq, bq, Wk, bk, Wv, bv, qp, kp, vp);
    // 4: attention + first residual (d_out = x + msa), tensor-core path
    attn_mma_kernel<<<dim3(NB * NH, NS / 128), 256, ATTN_SMEM_BYTES>>>(qp, kp, vp, x, out);
    // 5: LN2 (tf32-rounded)
    ln_kernel<1><<<NROWS, 256>>>(out, ln2_g, ln2_b, ln2p);
    // 6: FFN up + GELU
    gemm_mma<0><<<dim3(DFF / 128, NROWS / 128), 256, GEMM_SMEM_BYTES>>>(ln2p, w1tp, hidp, ND, DFF);
    // 7: FFN down + second residual
    gemm_mma<1><<<dim3(ND / 128, NROWS / 128), 256, GEMM_SMEM_BYTES>>>(hidp, w2tp, out, DFF, ND);
}

// round 9
// speedup vs baseline: 6.0025x; 3.5794x over previous
#include <cuda_runtime.h>
#include <cuda_fp16.h>
#include <math.h>
#include <stdint.h>

// Problem constants: B=8, S=1024, D=768, H=12, DH=64
#define NB 8
#define NS 1024
#define ND 768
#define NH 12
#define NDH 64
#define NROWS (NB * NS)          // 8192
#define DFF (4 * ND)             // 3072

// ---------------- scratch (device globals) ----------------------------------
__device__ __half g_ln1h[NROWS * ND];
__device__ __half g_qh[NROWS * ND];
__device__ __half g_kh[NROWS * ND];
__device__ __half g_vh[NROWS * ND];
__device__ __half g_ln2h[NROWS * ND];
__device__ __half g_hidh[(size_t)NROWS * DFF];     // 48 MB
__device__ __half g_w1th[DFF * ND];                // W1^T [3072][768]
__device__ __half g_w2th[ND * DFF];                // W2^T [768][3072]
__device__ __half g_wqkvh[3 * NH * 64 * 64];       // per-head W^T [mat][h][e][d]

// ---------------- helpers ----------------------------------------------------
__device__ __forceinline__ uint32_t smem_u32(const void* p) {
    uint32_t a;
    asm("{ .reg .u64 t; cvta.to.shared.u64 t, %1; cvt.u32.u64 %0, t; }" : "=r"(a) : "l"(p));
    return a;
}
__device__ __forceinline__ void cp_async16(uint32_t s, const void* g) {
    asm volatile("cp.async.cg.shared.global [%0], [%1], 16;" :: "r"(s), "l"(g));
}
__device__ __forceinline__ void mma_f16(
    float& c0, float& c1, float& c2, float& c3,
    uint32_t a0, uint32_t a1, uint32_t a2, uint32_t a3,
    uint32_t b0, uint32_t b1)
{
    asm volatile(
        "mma.sync.aligned.m16n8k16.row.col.f32.f16.f16.f32 "
        "{%0,%1,%2,%3}, {%4,%5,%6,%7}, {%8,%9}, {%0,%1,%2,%3};"
        : "+f"(c0), "+f"(c1), "+f"(c2), "+f"(c3)
        : "r"(a0), "r"(a1), "r"(a2), "r"(a3), "r"(b0), "r"(b1));
}
__device__ __forceinline__ void ldmatrix_x4_t(
    uint32_t& r0, uint32_t& r1, uint32_t& r2, uint32_t& r3, uint32_t addr)
{
    asm volatile("ldmatrix.sync.aligned.m8n8.x4.trans.shared.b16 {%0,%1,%2,%3}, [%4];"
        : "=r"(r0), "=r"(r1), "=r"(r2), "=r"(r3) : "r"(addr));
}
__device__ __forceinline__ float gelu_exact(float x) {
    return 0.5f * x * (1.0f + erff(x * 0.70710678118654752f));
}

// ---------------- LayerNorm -> fp16 output ----------------------------------
__global__ __launch_bounds__(256) void ln_half(
    const float* __restrict__ x, const float* __restrict__ gw,
    const float* __restrict__ bw, __half* __restrict__ out)
{
    __shared__ float r1[8], r2[8];
    int row = blockIdx.x, t = threadIdx.x;
    const float* xr = x + (size_t)row * ND;
    float v0 = xr[t], v1 = xr[t + 256], v2 = xr[t + 512];
    float s = v0 + v1 + v2;
#pragma unroll
    for (int o = 16; o > 0; o >>= 1) s += __shfl_xor_sync(0xffffffffu, s, o);
    if ((t & 31) == 0) r1[t >> 5] = s;
    __syncthreads();
    float tot = r1[0] + r1[1] + r1[2] + r1[3] + r1[4] + r1[5] + r1[6] + r1[7];
    float mean = tot * (1.0f / (float)ND);
    float d0 = v0 - mean, d1 = v1 - mean, d2 = v2 - mean;
    float sq = d0 * d0 + d1 * d1 + d2 * d2;
#pragma unroll
    for (int o = 16; o > 0; o >>= 1) sq += __shfl_xor_sync(0xffffffffu, sq, o);
    if ((t & 31) == 0) r2[t >> 5] = sq;
    __syncthreads();
    float var = (r2[0] + r2[1] + r2[2] + r2[3] + r2[4] + r2[5] + r2[6] + r2[7]) * (1.0f / (float)ND);
    float rstd = rsqrtf(var + 1e-5f);
    __half* orow = out + (size_t)row * ND;
    orow[t]       = __float2half_rn(d0 * rstd * gw[t]       + bw[t]);
    orow[t + 256] = __float2half_rn(d1 * rstd * gw[t + 256] + bw[t + 256]);
    orow[t + 512] = __float2half_rn(d2 * rstd * gw[t + 512] + bw[t + 512]);
}

// ---------------- transpose fp32 -> fp16: in[R][C] -> out[C][R] --------------
__global__ __launch_bounds__(256) void transpose_f16(
    const float* __restrict__ in, __half* __restrict__ out, int R, int C)
{
    __shared__ float tile[32][33];
    int c0 = blockIdx.x * 32, r0 = blockIdx.y * 32;
    int tx = threadIdx.x & 31, ty = threadIdx.x >> 5;
#pragma unroll
    for (int i = 0; i < 32; i += 8)
        tile[ty + i][tx] = in[(size_t)(r0 + ty + i) * C + c0 + tx];
    __syncthreads();
#pragma unroll
    for (int i = 0; i < 32; i += 8)
        out[(size_t)(c0 + ty + i) * R + r0 + tx] = __float2half_rn(tile[tx][ty + i]);
}

// ---------------- per-head weight transpose: W[h][d][e] -> half [m][h][e][d] -
__global__ __launch_bounds__(256) void wqkv_prep(
    const float* __restrict__ Wq, const float* __restrict__ Wk,
    const float* __restrict__ Wv, __half* __restrict__ out)
{
    int h = blockIdx.x, m = blockIdx.y;
    const float* W = (m == 0) ? Wq : ((m == 1) ? Wk : Wv);
    W += (size_t)h * 4096;
    __half* o = out + ((size_t)m * NH + h) * 4096;
    for (int idx = threadIdx.x; idx < 4096; idx += 256) {
        int d = idx >> 6, e = idx & 63;
        o[e * 64 + d] = __float2half_rn(W[d * 64 + e]);
    }
}

// ---------------- QKV: fp16 mma, CTA = 128 rows x 1 head --------------------
#define QS 72
#define QSW 36
#define QKV_SMEM ((128 * QS + 3 * 64 * QS) * 2)   // 46080 B

__global__ __launch_bounds__(256) void qkv_mma(
    const __half* __restrict__ ln1, const __half* __restrict__ wt,
    const float* __restrict__ bq, const float* __restrict__ bk,
    const float* __restrict__ bv,
    __half* __restrict__ q, __half* __restrict__ k, __half* __restrict__ v)
{
    extern __shared__ __half sh[];
    uint32_t sb = smem_u32(sh);
    uint32_t aW = sb + 128 * QS * 2;

    int bh = blockIdx.x;
    int h = bh % NH, b = bh / NH;
    int s0 = blockIdx.y * 128;
    int t = threadIdx.x, w = t >> 5, lane = t & 31;
    int gid = lane >> 2, tig = lane & 3;
    int rowb = (t & 7) + 8 * (t >> 5);
    int c0 = (t >> 3) & 3;

    const __half* Abase = ln1 + ((size_t)(b * NS + s0)) * ND + h * 64;
#pragma unroll
    for (int i = 0; i < 4; i++) {
        int row = rowb + 64 * (i >> 1);
        int c = c0 + 4 * (i & 1);
        cp_async16(sb + row * (QS * 2) + c * 16, Abase + (size_t)row * ND + c * 8);
    }
    const __half* Wbase = wt + (size_t)h * 4096;
#pragma unroll
    for (int m = 0; m < 3; m++)
#pragma unroll
        for (int i = 0; i < 2; i++) {
            int c = c0 + 4 * i;
            cp_async16(aW + m * (64 * QS * 2) + rowb * (QS * 2) + c * 16,
                       Wbase + (size_t)m * (NH * 4096) + rowb * 64 + c * 8);
        }
    asm volatile("cp.async.commit_group;\n\tcp.async.wait_group 0;" ::: "memory");
    __syncthreads();

    const uint32_t* Au = (const uint32_t*)sh;
    const uint32_t* Wu = (const uint32_t*)(sh + 128 * QS);
    int wrow = w * 16;

    uint32_t af[4][4];
#pragma unroll
    for (int kc = 0; kc < 4; kc++) {
        af[kc][0] = Au[(wrow + gid) * QSW + kc * 8 + tig];
        af[kc][1] = Au[(wrow + gid + 8) * QSW + kc * 8 + tig];
        af[kc][2] = Au[(wrow + gid) * QSW + kc * 8 + 4 + tig];
        af[kc][3] = Au[(wrow + gid + 8) * QSW + kc * 8 + 4 + tig];
    }
    float acc[3][8][4];
#pragma unroll
    for (int m = 0; m < 3; m++)
#pragma unroll
        for (int nf = 0; nf < 8; nf++)
#pragma unroll
            for (int r = 0; r < 4; r++) acc[m][nf][r] = 0.f;

#pragma unroll
    for (int kc = 0; kc < 4; kc++)
#pragma unroll
        for (int m = 0; m < 3; m++)
#pragma unroll
            for (int nf = 0; nf < 8; nf++) {
                uint32_t b0 = Wu[m * (64 * QSW) + (nf * 8 + gid) * QSW + kc * 8 + tig];
                uint32_t b1 = Wu[m * (64 * QSW) + (nf * 8 + gid) * QSW + kc * 8 + 4 + tig];
                mma_f16(acc[m][nf][0], acc[m][nf][1], acc[m][nf][2], acc[m][nf][3],
                        af[kc][0], af[kc][1], af[kc][2], af[kc][3], b0, b1);
            }

    size_t grow0 = (size_t)bh * NS + s0 + wrow + gid;
    size_t grow1 = grow0 + 8;
    const float* biases[3] = { bq + h * 64, bk + h * 64, bv + h * 64 };
    __half* dsts[3] = { q, k, v };
#pragma unroll
    for (int m = 0; m < 3; m++) {
        __half2* D = (__half2*)dsts[m];
        const float* bi = biases[m];
#pragma unroll
        for (int nf = 0; nf < 8; nf++) {
            int col = nf * 8 + 2 * tig;
            float b0 = bi[col], b1 = bi[col + 1];
            float v00 = acc[m][nf][0] + b0, v01 = acc[m][nf][1] + b1;
            float v10 = acc[m][nf][2] + b0, v11 = acc[m][nf][3] + b1;
            if (m == 0) { v00 *= 0.125f; v01 *= 0.125f; v10 *= 0.125f; v11 *= 0.125f; }
            D[grow0 * 32 + nf * 4 + tig] = __floats2half2_rn(v00, v01);
            D[grow1 * 32 + nf * 4 + tig] = __floats2half2_rn(v10, v11);
        }
    }
}

// ---------------- Attention: fp16 mma flash, ldmatrix.trans for V -----------
#define AS 72
#define ASW 36
#define ATTN_SMEM ((64 * AS + 64 * AS + 128 * AS) * 2)   // 36864 B

__global__ __launch_bounds__(256) void attn_h(
    const __half* __restrict__ q, const __half* __restrict__ k,
    const __half* __restrict__ v, const float* __restrict__ x,
    float* __restrict__ out)
{
    extern __shared__ __half sh[];
    __half* Ks = sh;
    __half* Vs = sh + 64 * AS;
    __half* Ps = sh + 128 * AS;
    uint32_t sbK = smem_u32(Ks);
    uint32_t sbV = sbK + 64 * AS * 2;

    int bh = blockIdx.x;
    int h = bh % NH, b = bh / NH;
    int t = threadIdx.x, w = t >> 5, lane = t & 31;
    int gid = lane >> 2, tig = lane & 3;
    int qbase = blockIdx.y * 128;
    int wrow = w * 16;
    int rowb = (t & 7) + 8 * (t >> 5);   // 0..63
    int c0 = (t >> 3) & 3;

    // Q fragments (already pre-scaled by 1/8 in qkv_mma)
    uint32_t qf[4][4];
    {
        const uint32_t* Qu = (const uint32_t*)(q + ((size_t)bh * NS + qbase + wrow) * NDH);
#pragma unroll
        for (int kc = 0; kc < 4; kc++) {
            qf[kc][0] = Qu[gid * 32 + kc * 8 + tig];
            qf[kc][1] = Qu[(gid + 8) * 32 + kc * 8 + tig];
            qf[kc][2] = Qu[gid * 32 + kc * 8 + 4 + tig];
            qf[kc][3] = Qu[(gid + 8) * 32 + kc * 8 + 4 + tig];
        }
    }

    float oa[8][4];
#pragma unroll
    for (int nf = 0; nf < 8; nf++) { oa[nf][0] = oa[nf][1] = oa[nf][2] = oa[nf][3] = 0.f; }
    float m0 = -1e30f, m1 = -1e30f, l0 = 0.f, l1 = 0.f;

    const uint32_t* Ku = (const uint32_t*)Ks;
    const uint32_t* Pu = (const uint32_t*)Ps;
    __half2* Ph2 = (__half2*)Ps;

    for (int kt = 0; kt < 16; kt++) {
        __syncthreads();
        const __half* Kg = k + ((size_t)bh * NS + kt * 64) * NDH;
        const __half* Vg = v + ((size_t)bh * NS + kt * 64) * NDH;
#pragma unroll
        for (int i = 0; i < 2; i++) {
            int c = c0 + 4 * i;
            cp_async16(sbK + rowb * (AS * 2) + c * 16, Kg + (size_t)rowb * NDH + c * 8);
            cp_async16(sbV + rowb * (AS * 2) + c * 16, Vg + (size_t)rowb * NDH + c * 8);
        }
        asm volatile("cp.async.commit_group;\n\tcp.async.wait_group 0;" ::: "memory");
        __syncthreads();

        // S = (Q/8) K^T
        float sa[8][4];
#pragma unroll
        for (int nf = 0; nf < 8; nf++) { sa[nf][0] = sa[nf][1] = sa[nf][2] = sa[nf][3] = 0.f; }
#pragma unroll
        for (int kc = 0; kc < 4; kc++)
#pragma unroll
            for (int nf = 0; nf < 8; nf++) {
                uint32_t b0 = Ku[(nf * 8 + gid) * ASW + kc * 8 + tig];
                uint32_t b1 = Ku[(nf * 8 + gid) * ASW + kc * 8 + 4 + tig];
                mma_f16(sa[nf][0], sa[nf][1], sa[nf][2], sa[nf][3],
                        qf[kc][0], qf[kc][1], qf[kc][2], qf[kc][3], b0, b1);
            }

        // online softmax (rows gid / gid+8)
        float tm0 = -1e30f, tm1 = -1e30f;
#pragma unroll
        for (int nf = 0; nf < 8; nf++) {
            tm0 = fmaxf(tm0, fmaxf(sa[nf][0], sa[nf][1]));
            tm1 = fmaxf(tm1, fmaxf(sa[nf][2], sa[nf][3]));
        }
        tm0 = fmaxf(tm0, __shfl_xor_sync(0xffffffffu, tm0, 1));
        tm0 = fmaxf(tm0, __shfl_xor_sync(0xffffffffu, tm0, 2));
        tm1 = fmaxf(tm1, __shfl_xor_sync(0xffffffffu, tm1, 1));
        tm1 = fmaxf(tm1, __shfl_xor_sync(0xffffffffu, tm1, 2));
        float mn0 = fmaxf(m0, tm0), mn1 = fmaxf(m1, tm1);
        float cc0 = __expf(m0 - mn0), cc1 = __expf(m1 - mn1);
        m0 = mn0; m1 = mn1;

        float ls0 = 0.f, ls1 = 0.f;
#pragma unroll
        for (int nf = 0; nf < 8; nf++) {
            float p00 = __expf(sa[nf][0] - mn0);
            float p01 = __expf(sa[nf][1] - mn0);
            float p10 = __expf(sa[nf][2] - mn1);
            float p11 = __expf(sa[nf][3] - mn1);
            ls0 += p00 + p01;
            ls1 += p10 + p11;
            Ph2[(wrow + gid) * ASW + nf * 4 + tig] = __floats2half2_rn(p00, p01);
            Ph2[(wrow + gid + 8) * ASW + nf * 4 + tig] = __floats2half2_rn(p10, p11);
        }
        ls0 += __shfl_xor_sync(0xffffffffu, ls0, 1);
        ls0 += __shfl_xor_sync(0xffffffffu, ls0, 2);
        ls1 += __shfl_xor_sync(0xffffffffu, ls1, 1);
        ls1 += __shfl_xor_sync(0xffffffffu, ls1, 2);
        l0 = l0 * cc0 + ls0;
        l1 = l1 * cc1 + ls1;
#pragma unroll
        for (int nf = 0; nf < 8; nf++) {
            oa[nf][0] *= cc0; oa[nf][1] *= cc0;
            oa[nf][2] *= cc1; oa[nf][3] *= cc1;
        }
        __syncwarp();

        // O += P V  (V B-frags via ldmatrix.x4.trans)
        int g = lane >> 3, r = lane & 7;
#pragma unroll
        for (int kc = 0; kc < 4; kc++) {
            uint32_t a0 = Pu[(wrow + gid) * ASW + kc * 8 + tig];
            uint32_t a1 = Pu[(wrow + gid + 8) * ASW + kc * 8 + tig];
            uint32_t a2 = Pu[(wrow + gid) * ASW + kc * 8 + 4 + tig];
            uint32_t a3 = Pu[(wrow + gid + 8) * ASW + kc * 8 + 4 + tig];
#pragma unroll
            for (int nf2 = 0; nf2 < 4; nf2++) {
                uint32_t addr = sbV + (kc * 16 + (g & 1) * 8 + r) * (AS * 2)
                                    + nf2 * 32 + (g >> 1) * 16;
                uint32_t r0, r1, r2, r3;
                ldmatrix_x4_t(r0, r1, r2, r3, addr);
                mma_f16(oa[2 * nf2][0], oa[2 * nf2][1], oa[2 * nf2][2], oa[2 * nf2][3],
                        a0, a1, a2, a3, r0, r1);
                mma_f16(oa[2 * nf2 + 1][0], oa[2 * nf2 + 1][1], oa[2 * nf2 + 1][2], oa[2 * nf2 + 1][3],
                        a0, a1, a2, a3, r2, r3);
            }
        }
        __syncwarp();
    }

    float inv0 = 1.f / l0, inv1 = 1.f / l1;
    int r0g = qbase + wrow + gid;
    size_t o0 = ((size_t)(b * NS) + r0g) * ND + h * NDH;
    size_t o1 = o0 + (size_t)8 * ND;
#pragma unroll
    for (int nf = 0; nf < 8; nf++) {
        int col = nf * 8 + 2 * tig;
        float2 x0 = *(const float2*)(x + o0 + col);
        float2 x1 = *(const float2*)(x + o1 + col);
        *(float2*)(out + o0 + col) = make_float2(x0.x + oa[nf][0] * inv0, x0.y + oa[nf][1] * inv0);
        *(float2*)(out + o1 + col) = make_float2(x1.x + oa[nf][2] * inv1, x1.y + oa[nf][3] * inv1);
    }
}

// ---------------- FFN fp16 GEMM: 128x128 tile, Ktile 32, double buffer ------
#define FS 40
#define FSW 20
#define FBUF (128 * FS)                 // halves per buffer
#define GEMM_SMEM (4 * FBUF * 2)        // 40960 B

template <int EPI>
__global__ __launch_bounds__(256) void gemm_h(
    const __half* __restrict__ A, const __half* __restrict__ Bt,
    void* __restrict__ Cv, int K, int N)
{
    extern __shared__ __half sh[];
    uint32_t sb = smem_u32(sh);

    int t = threadIdx.x, w = t >> 5, lane = t & 31;
    int gid = lane >> 2, tig = lane & 3;
    int wm = w >> 2, wn = w & 3;
    int m0 = blockIdx.y * 128, n0 = blockIdx.x * 128;
    int rowb = (t & 7) + 8 * (t >> 5);   // 0..63
    int c0 = (t >> 3) & 3;

    const __half* Ag = A + (size_t)m0 * K;
    const __half* Bg = Bt + (size_t)n0 * K;

    float acc[4][4][4];
#pragma unroll
    for (int i = 0; i < 4; i++)
#pragma unroll
        for (int j = 0; j < 4; j++)
#pragma unroll
            for (int r = 0; r < 4; r++) acc[i][j][r] = 0.f;

    int nkt = K >> 5;
    // prefetch kt=0 -> buffer 0
    {
        uint32_t dA = sb, dB = sb + FBUF * 2;
#pragma unroll
        for (int i = 0; i < 2; i++) {
            int row = rowb + 64 * i;
            cp_async16(dA + row * (FS * 2) + c0 * 16, Ag + (size_t)row * K + c0 * 8);
            cp_async16(dB + row * (FS * 2) + c0 * 16, Bg + (size_t)row * K + c0 * 8);
        }
        asm volatile("cp.async.commit_group;" ::: "memory");
    }

    for (int kt = 0; kt < nkt; kt++) {
        int cur = kt & 1;
        if (kt + 1 < nkt) {
            int nxt = cur ^ 1;
            uint32_t dA = sb + nxt * (2 * FBUF * 2), dB = dA + FBUF * 2;
            int kh = (kt + 1) * 32;
#pragma unroll
            for (int i = 0; i < 2; i++) {
                int row = rowb + 64 * i;
                cp_async16(dA + row * (FS * 2) + c0 * 16, Ag + (size_t)row * K + kh + c0 * 8);
                cp_async16(dB + row * (FS * 2) + c0 * 16, Bg + (size_t)row * K + kh + c0 * 8);
            }
            asm volatile("cp.async.commit_group;\n\tcp.async.wait_group 1;" ::: "memory");
        } else {
            asm volatile("cp.async.wait_group 0;" ::: "memory");
        }
        __syncthreads();

        const uint32_t* Au = (const uint32_t*)(sh + cur * 2 * FBUF);
        const uint32_t* Bu = Au + FBUF / 2;

#pragma unroll
        for (int ks = 0; ks < 2; ks++) {
            uint32_t a[4][4];
#pragma unroll
            for (int mf = 0; mf < 4; mf++) {
                int row = wm * 64 + mf * 16 + gid;
                a[mf][0] = Au[row * FSW + ks * 8 + tig];
                a[mf][1] = Au[(row + 8) * FSW + ks * 8 + tig];
                a[mf][2] = Au[row * FSW + ks * 8 + 4 + tig];
                a[mf][3] = Au[(row + 8) * FSW + ks * 8 + 4 + tig];
            }
            uint32_t bb[4][2];
#pragma unroll
            for (int nf = 0; nf < 4; nf++) {
                int rb = wn * 32 + nf * 8 + gid;
                bb[nf][0] = Bu[rb * FSW + ks * 8 + tig];
                bb[nf][1] = Bu[rb * FSW + ks * 8 + 4 + tig];
            }
#pragma unroll
            for (int mf = 0; mf < 4; mf++)
#pragma unroll
                for (int nf = 0; nf < 4; nf++)
                    mma_f16(acc[mf][nf][0], acc[mf][nf][1], acc[mf][nf][2], acc[mf][nf][3],
                            a[mf][0], a[mf][1], a[mf][2], a[mf][3],
                            bb[nf][0], bb[nf][1]);
        }
        __syncthreads();
    }

#pragma unroll
    for (int mf = 0; mf < 4; mf++) {
#pragma unroll
        for (int nf = 0; nf < 4; nf++) {
            int row = m0 + wm * 64 + mf * 16 + gid;
            int col = n0 + wn * 32 + nf * 8 + tig * 2;
            if (EPI == 0) {
                __half2* C = (__half2*)Cv;
                C[(size_t)row * (N / 2) + col / 2] =
                    __floats2half2_rn(gelu_exact(acc[mf][nf][0]), gelu_exact(acc[mf][nf][1]));
                C[(size_t)(row + 8) * (N / 2) + col / 2] =
                    __floats2half2_rn(gelu_exact(acc[mf][nf][2]), gelu_exact(acc[mf][nf][3]));
            } else {
                float* C = (float*)Cv;
                float* p0 = C + (size_t)row * N + col;
                float* p1 = C + (size_t)(row + 8) * N + col;
                float2 c0v = *(float2*)p0, c1v = *(float2*)p1;
                *(float2*)p0 = make_float2(c0v.x + acc[mf][nf][0], c0v.y + acc[mf][nf][1]);
                *(float2*)p1 = make_float2(c1v.x + acc[mf][nf][2], c1v.y + acc[mf][nf][3]);
            }
        }
    }
}

// ---------------- host launcher ---------------------------------------------
extern "C" void kernel_launch(void* const* d_in, const int* in_sizes, int n_in,
                              void* d_out, int out_size)
{
    const float* x     = (const float*)d_in[0];
    const float* ln1_g = (const float*)d_in[1];
    const float* ln1_b = (const float*)d_in[2];
    const float* Wq    = (const float*)d_in[3];
    const float* bq    = (const float*)d_in[4];
    const float* Wk    = (const float*)d_in[5];
    const float* bk    = (const float*)d_in[6];
    const float* Wv    = (const float*)d_in[7];
    const float* bv    = (const float*)d_in[8];
    const float* ln2_g = (const float*)d_in[9];
    const float* ln2_b = (const float*)d_in[10];
    const float* W1    = (const float*)d_in[11];
    const float* W2    = (const float*)d_in[12];
    float* out = (float*)d_out;

    __half *ln1p, *qp, *kp, *vp, *ln2p, *hidp, *w1tp, *w2tp, *wqkvp;
    cudaGetSymbolAddress((void**)&ln1p,  g_ln1h);
    cudaGetSymbolAddress((void**)&qp,    g_qh);
    cudaGetSymbolAddress((void**)&kp,    g_kh);
    cudaGetSymbolAddress((void**)&vp,    g_vh);
    cudaGetSymbolAddress((void**)&ln2p,  g_ln2h);
    cudaGetSymbolAddress((void**)&hidp,  g_hidh);
    cudaGetSymbolAddress((void**)&w1tp,  g_w1th);
    cudaGetSymbolAddress((void**)&w2tp,  g_w2th);
    cudaGetSymbolAddress((void**)&wqkvp, g_wqkvh);

    cudaFuncSetAttribute(qkv_mma,   cudaFuncAttributeMaxDynamicSharedMemorySize, QKV_SMEM);
    cudaFuncSetAttribute(attn_h,    cudaFuncAttributeMaxDynamicSharedMemorySize, ATTN_SMEM);
    cudaFuncSetAttribute(gemm_h<0>, cudaFuncAttributeMaxDynamicSharedMemorySize, GEMM_SMEM);
    cudaFuncSetAttribute(gemm_h<1>, cudaFuncAttributeMaxDynamicSharedMemorySize, GEMM_SMEM);

    // weight preps
    transpose_f16<<<dim3(DFF / 32, ND / 32), 256>>>(W1, w1tp, ND, DFF);   // [3072][768]
    transpose_f16<<<dim3(ND / 32, DFF / 32), 256>>>(W2, w2tp, DFF, ND);   // [768][3072]
    wqkv_prep<<<dim3(NH, 3), 256>>>(Wq, Wk, Wv, wqkvp);
    // LN1 -> fp16
    ln_half<<<NROWS, 256>>>(x, ln1_g, ln1_b, ln1p);
    // QKV (fp16 mma, Q pre-scaled by 1/8)
    qkv_mma<<<dim3(NB * NH, NS / 128), 256, QKV_SMEM>>>(ln1p, wqkvp, bq, bk, bv, qp, kp, vp);
    // attention + residual (out = x + msa)
    attn_h<<<dim3(NB * NH, NS / 128), 256, ATTN_SMEM>>>(qp, kp, vp, x, out);
    // LN2 -> fp16
    ln_half<<<NROWS, 256>>>(out, ln2_g, ln2_b, ln2p);
    // FFN up + GELU -> fp16 hid
    gemm_h<0><<<dim3(DFF / 128, NROWS / 128), 256, GEMM_SMEM>>>(ln2p, w1tp, (void*)hidp, ND, DFF);
    // FFN down + residual into out
    gemm_h<1><<<dim3(ND / 128, NROWS / 128), 256, GEMM_SMEM>>>(hidp, w2tp, (void*)out, DFF, ND);
}

// round 12
// speedup vs baseline: 7.0338x; 1.1718x over previous
#include <cuda_runtime.h>
#include <cuda_fp16.h>
#include <math.h>
#include <stdint.h>

// Problem constants: B=8, S=1024, D=768, H=12, DH=64
#define NB 8
#define NS 1024
#define ND 768
#define NH 12
#define NDH 64
#define NROWS (NB * NS)          // 8192
#define DFF (4 * ND)             // 3072

// ---------------- scratch (device globals) ----------------------------------
__device__ __half g_ln1h[NROWS * ND];
__device__ __half g_qh[NROWS * ND];
__device__ __half g_kh[NROWS * ND];
__device__ __half g_vh[NROWS * ND];
__device__ __half g_ln2h[NROWS * ND];
__device__ __half g_hidh[(size_t)NROWS * DFF];     // 48 MB
__device__ __half g_w1th[DFF * ND];                // W1^T [3072][768]
__device__ __half g_w2th[ND * DFF];                // W2^T [768][3072]
__device__ __half g_wqkvh[3 * NH * 64 * 64];       // per-head W^T [mat][h][e][d]

// ---------------- helpers ----------------------------------------------------
__device__ __forceinline__ uint32_t smem_u32(const void* p) {
    uint32_t a;
    asm("{ .reg .u64 t; cvta.to.shared.u64 t, %1; cvt.u32.u64 %0, t; }" : "=r"(a) : "l"(p));
    return a;
}
__device__ __forceinline__ void cp_async16(uint32_t s, const void* g) {
    asm volatile("cp.async.cg.shared.global [%0], [%1], 16;" :: "r"(s), "l"(g));
}
__device__ __forceinline__ void mma_f16(
    float& c0, float& c1, float& c2, float& c3,
    uint32_t a0, uint32_t a1, uint32_t a2, uint32_t a3,
    uint32_t b0, uint32_t b1)
{
    asm volatile(
        "mma.sync.aligned.m16n8k16.row.col.f32.f16.f16.f32 "
        "{%0,%1,%2,%3}, {%4,%5,%6,%7}, {%8,%9}, {%0,%1,%2,%3};"
        : "+f"(c0), "+f"(c1), "+f"(c2), "+f"(c3)
        : "r"(a0), "r"(a1), "r"(a2), "r"(a3), "r"(b0), "r"(b1));
}
__device__ __forceinline__ void ldmatrix_x4(
    uint32_t& r0, uint32_t& r1, uint32_t& r2, uint32_t& r3, uint32_t addr)
{
    asm volatile("ldmatrix.sync.aligned.m8n8.x4.shared.b16 {%0,%1,%2,%3}, [%4];"
        : "=r"(r0), "=r"(r1), "=r"(r2), "=r"(r3) : "r"(addr));
}
__device__ __forceinline__ void ldmatrix_x4_t(
    uint32_t& r0, uint32_t& r1, uint32_t& r2, uint32_t& r3, uint32_t addr)
{
    asm volatile("ldmatrix.sync.aligned.m8n8.x4.trans.shared.b16 {%0,%1,%2,%3}, [%4];"
        : "=r"(r0), "=r"(r1), "=r"(r2), "=r"(r3) : "r"(addr));
}
__device__ __forceinline__ float gelu_exact(float x) {
    return 0.5f * x * (1.0f + erff(x * 0.70710678118654752f));
}

// ---------------- LayerNorm -> fp16 output ----------------------------------
__global__ __launch_bounds__(256) void ln_half(
    const float* __restrict__ x, const float* __restrict__ gw,
    const float* __restrict__ bw, __half* __restrict__ out)
{
    __shared__ float r1[8], r2[8];
    int row = blockIdx.x, t = threadIdx.x;
    const float* xr = x + (size_t)row * ND;
    float v0 = xr[t], v1 = xr[t + 256], v2 = xr[t + 512];
    float s = v0 + v1 + v2;
#pragma unroll
    for (int o = 16; o > 0; o >>= 1) s += __shfl_xor_sync(0xffffffffu, s, o);
    if ((t & 31) == 0) r1[t >> 5] = s;
    __syncthreads();
    float tot = r1[0] + r1[1] + r1[2] + r1[3] + r1[4] + r1[5] + r1[6] + r1[7];
    float mean = tot * (1.0f / (float)ND);
    float d0 = v0 - mean, d1 = v1 - mean, d2 = v2 - mean;
    float sq = d0 * d0 + d1 * d1 + d2 * d2;
#pragma unroll
    for (int o = 16; o > 0; o >>= 1) sq += __shfl_xor_sync(0xffffffffu, sq, o);
    if ((t & 31) == 0) r2[t >> 5] = sq;
    __syncthreads();
    float var = (r2[0] + r2[1] + r2[2] + r2[3] + r2[4] + r2[5] + r2[6] + r2[7]) * (1.0f / (float)ND);
    float rstd = rsqrtf(var + 1e-5f);
    __half* orow = out + (size_t)row * ND;
    orow[t]       = __float2half_rn(d0 * rstd * gw[t]       + bw[t]);
    orow[t + 256] = __float2half_rn(d1 * rstd * gw[t + 256] + bw[t + 256]);
    orow[t + 512] = __float2half_rn(d2 * rstd * gw[t + 512] + bw[t + 512]);
}

// ---------------- transpose fp32 -> fp16: in[R][C] -> out[C][R] --------------
__global__ __launch_bounds__(256) void transpose_f16(
    const float* __restrict__ in, __half* __restrict__ out, int R, int C)
{
    __shared__ float tile[32][33];
    int c0 = blockIdx.x * 32, r0 = blockIdx.y * 32;
    int tx = threadIdx.x & 31, ty = threadIdx.x >> 5;
#pragma unroll
    for (int i = 0; i < 32; i += 8)
        tile[ty + i][tx] = in[(size_t)(r0 + ty + i) * C + c0 + tx];
    __syncthreads();
#pragma unroll
    for (int i = 0; i < 32; i += 8)
        out[(size_t)(c0 + ty + i) * R + r0 + tx] = __float2half_rn(tile[tx][ty + i]);
}

// ---------------- per-head weight transpose: W[h][d][e] -> half [m][h][e][d] -
__global__ __launch_bounds__(256) void wqkv_prep(
    const float* __restrict__ Wq, const float* __restrict__ Wk,
    const float* __restrict__ Wv, __half* __restrict__ out)
{
    int h = blockIdx.x, m = blockIdx.y;
    const float* W = (m == 0) ? Wq : ((m == 1) ? Wk : Wv);
    W += (size_t)h * 4096;
    __half* o = out + ((size_t)m * NH + h) * 4096;
    for (int idx = threadIdx.x; idx < 4096; idx += 256) {
        int d = idx >> 6, e = idx & 63;
        o[e * 64 + d] = __float2half_rn(W[d * 64 + e]);
    }
}

// ---------------- QKV: fp16 mma, CTA = 128 rows x 1 head --------------------
#define QS 72
#define QSW 36
#define QKV_SMEM ((128 * QS + 3 * 64 * QS) * 2)   // 46080 B

__global__ __launch_bounds__(256) void qkv_mma(
    const __half* __restrict__ ln1, const __half* __restrict__ wt,
    const float* __restrict__ bq, const float* __restrict__ bk,
    const float* __restrict__ bv,
    __half* __restrict__ q, __half* __restrict__ k, __half* __restrict__ v)
{
    extern __shared__ __half sh[];
    uint32_t sb = smem_u32(sh);
    uint32_t aW = sb + 128 * QS * 2;

    int bh = blockIdx.x;
    int h = bh % NH, b = bh / NH;
    int s0 = blockIdx.y * 128;
    int t = threadIdx.x, w = t >> 5, lane = t & 31;
    int gid = lane >> 2, tig = lane & 3;
    int rowb = (t & 7) + 8 * (t >> 5);
    int c0 = (t >> 3) & 3;

    const __half* Abase = ln1 + ((size_t)(b * NS + s0)) * ND + h * 64;
#pragma unroll
    for (int i = 0; i < 4; i++) {
        int row = rowb + 64 * (i >> 1);
        int c = c0 + 4 * (i & 1);
        cp_async16(sb + row * (QS * 2) + c * 16, Abase + (size_t)row * ND + c * 8);
    }
    const __half* Wbase = wt + (size_t)h * 4096;
#pragma unroll
    for (int m = 0; m < 3; m++)
#pragma unroll
        for (int i = 0; i < 2; i++) {
            int c = c0 + 4 * i;
            cp_async16(aW + m * (64 * QS * 2) + rowb * (QS * 2) + c * 16,
                       Wbase + (size_t)m * (NH * 4096) + rowb * 64 + c * 8);
        }
    asm volatile("cp.async.commit_group;\n\tcp.async.wait_group 0;" ::: "memory");
    __syncthreads();

    const uint32_t* Au = (const uint32_t*)sh;
    const uint32_t* Wu = (const uint32_t*)(sh + 128 * QS);
    int wrow = w * 16;

    uint32_t af[4][4];
#pragma unroll
    for (int kc = 0; kc < 4; kc++) {
        af[kc][0] = Au[(wrow + gid) * QSW + kc * 8 + tig];
        af[kc][1] = Au[(wrow + gid + 8) * QSW + kc * 8 + tig];
        af[kc][2] = Au[(wrow + gid) * QSW + kc * 8 + 4 + tig];
        af[kc][3] = Au[(wrow + gid + 8) * QSW + kc * 8 + 4 + tig];
    }
    float acc[3][8][4];
#pragma unroll
    for (int m = 0; m < 3; m++)
#pragma unroll
        for (int nf = 0; nf < 8; nf++)
#pragma unroll
            for (int r = 0; r < 4; r++) acc[m][nf][r] = 0.f;

#pragma unroll
    for (int kc = 0; kc < 4; kc++)
#pragma unroll
        for (int m = 0; m < 3; m++)
#pragma unroll
            for (int nf = 0; nf < 8; nf++) {
                uint32_t b0 = Wu[m * (64 * QSW) + (nf * 8 + gid) * QSW + kc * 8 + tig];
                uint32_t b1 = Wu[m * (64 * QSW) + (nf * 8 + gid) * QSW + kc * 8 + 4 + tig];
                mma_f16(acc[m][nf][0], acc[m][nf][1], acc[m][nf][2], acc[m][nf][3],
                        af[kc][0], af[kc][1], af[kc][2], af[kc][3], b0, b1);
            }

    size_t grow0 = (size_t)bh * NS + s0 + wrow + gid;
    size_t grow1 = grow0 + 8;
    const float* biases[3] = { bq + h * 64, bk + h * 64, bv + h * 64 };
    __half* dsts[3] = { q, k, v };
#pragma unroll
    for (int m = 0; m < 3; m++) {
        __half2* D = (__half2*)dsts[m];
        const float* bi = biases[m];
#pragma unroll
        for (int nf = 0; nf < 8; nf++) {
            int col = nf * 8 + 2 * tig;
            float b0 = bi[col], b1 = bi[col + 1];
            float v00 = acc[m][nf][0] + b0, v01 = acc[m][nf][1] + b1;
            float v10 = acc[m][nf][2] + b0, v11 = acc[m][nf][3] + b1;
            if (m == 0) { v00 *= 0.125f; v01 *= 0.125f; v10 *= 0.125f; v11 *= 0.125f; }
            D[grow0 * 32 + nf * 4 + tig] = __floats2half2_rn(v00, v01);
            D[grow1 * 32 + nf * 4 + tig] = __floats2half2_rn(v10, v11);
        }
    }
}

// ---------------- Attention: fp16 mma flash, double-buffered K/V ------------
// smem layout (halves): K0,K1 [64*AS each] | V0,V1 [64*AS each] | P [128*AS]
#define AS 72
#define ASW 36
#define ATTN_SMEM ((4 * 64 * AS + 128 * AS) * 2)   // 55296 B

__global__ __launch_bounds__(256) void attn_h(
    const __half* __restrict__ q, const __half* __restrict__ k,
    const __half* __restrict__ v, const float* __restrict__ x,
    float* __restrict__ out)
{
    extern __shared__ __half sh[];
    uint32_t sb = smem_u32(sh);
    uint32_t sbP = sb + (4 * 64 * AS) * 2;

    int bh = blockIdx.x;
    int h = bh % NH, b = bh / NH;
    int t = threadIdx.x, w = t >> 5, lane = t & 31;
    int gid = lane >> 2, tig = lane & 3;
    int qbase = blockIdx.y * 128;
    int wrow = w * 16;

    // Q fragments (pre-scaled by 1/8 in qkv_mma)
    uint32_t qf[4][4];
    {
        const uint32_t* Qu = (const uint32_t*)(q + ((size_t)bh * NS + qbase + wrow) * NDH);
#pragma unroll
        for (int kc = 0; kc < 4; kc++) {
            qf[kc][0] = Qu[gid * 32 + kc * 8 + tig];
            qf[kc][1] = Qu[(gid + 8) * 32 + kc * 8 + tig];
            qf[kc][2] = Qu[gid * 32 + kc * 8 + 4 + tig];
            qf[kc][3] = Qu[(gid + 8) * 32 + kc * 8 + 4 + tig];
        }
    }

    float oa[8][4];
#pragma unroll
    for (int nf = 0; nf < 8; nf++) { oa[nf][0] = oa[nf][1] = oa[nf][2] = oa[nf][3] = 0.f; }
    float m0 = -1e30f, m1 = -1e30f, l0 = 0.f, l1 = 0.f;

    const __half* Kg0 = k + (size_t)bh * NS * NDH;
    const __half* Vg0 = v + (size_t)bh * NS * NDH;
    int lrow = t >> 3, lc = t & 7;       // 8 lanes cover one 128B row chunk-range

    // prefetch tile 0 into stage 0
    {
        const __half* Kg = Kg0;
        const __half* Vg = Vg0;
#pragma unroll
        for (int p = 0; p < 2; p++) {
            int row = lrow + p * 32;
            cp_async16(sb + row * (AS * 2) + lc * 16, Kg + (size_t)row * NDH + lc * 8);
            cp_async16(sb + (2 * 64 * AS) * 2 + row * (AS * 2) + lc * 16,
                       Vg + (size_t)row * NDH + lc * 8);
        }
        asm volatile("cp.async.commit_group;" ::: "memory");
    }

    __half2* Ph2 = (__half2*)(sh + 4 * 64 * AS);

    for (int kt = 0; kt < 16; kt++) {
        int cur = kt & 1, nxt = cur ^ 1;
        __syncthreads();   // everyone done reading stage nxt (= kt-1's buffer)
        if (kt + 1 < 16) {
            const __half* Kg = Kg0 + (size_t)(kt + 1) * 64 * NDH;
            const __half* Vg = Vg0 + (size_t)(kt + 1) * 64 * NDH;
            uint32_t kb = sb + nxt * (64 * AS * 2);
            uint32_t vb = sb + (2 * 64 * AS) * 2 + nxt * (64 * AS * 2);
#pragma unroll
            for (int p = 0; p < 2; p++) {
                int row = lrow + p * 32;
                cp_async16(kb + row * (AS * 2) + lc * 16, Kg + (size_t)row * NDH + lc * 8);
                cp_async16(vb + row * (AS * 2) + lc * 16, Vg + (size_t)row * NDH + lc * 8);
            }
            asm volatile("cp.async.commit_group;\n\tcp.async.wait_group 1;" ::: "memory");
        } else {
            asm volatile("cp.async.wait_group 0;" ::: "memory");
        }
        __syncthreads();

        uint32_t kbase = sb + cur * (64 * AS * 2);
        uint32_t vbase = sb + (2 * 64 * AS) * 2 + cur * (64 * AS * 2);

        // S = (Q/8) K^T  (K B-frags via ldmatrix.x4, 2 n-tiles per load)
        float sa[8][4];
#pragma unroll
        for (int nf = 0; nf < 8; nf++) { sa[nf][0] = sa[nf][1] = sa[nf][2] = sa[nf][3] = 0.f; }
#pragma unroll
        for (int kc = 0; kc < 4; kc++)
#pragma unroll
            for (int nf2 = 0; nf2 < 4; nf2++) {
                int nrow = (2 * nf2 + ((lane >> 4) & 1)) * 8 + (lane & 7);
                uint32_t addr = kbase + nrow * (AS * 2) + kc * 32 + ((lane >> 3) & 1) * 16;
                uint32_t b0, b1, b2, b3;
                ldmatrix_x4(b0, b1, b2, b3, addr);
                mma_f16(sa[2 * nf2][0], sa[2 * nf2][1], sa[2 * nf2][2], sa[2 * nf2][3],
                        qf[kc][0], qf[kc][1], qf[kc][2], qf[kc][3], b0, b1);
                mma_f16(sa[2 * nf2 + 1][0], sa[2 * nf2 + 1][1], sa[2 * nf2 + 1][2], sa[2 * nf2 + 1][3],
                        qf[kc][0], qf[kc][1], qf[kc][2], qf[kc][3], b2, b3);
            }

        // online softmax (rows gid / gid+8)
        float tm0 = -1e30f, tm1 = -1e30f;
#pragma unroll
        for (int nf = 0; nf < 8; nf++) {
            tm0 = fmaxf(tm0, fmaxf(sa[nf][0], sa[nf][1]));
            tm1 = fmaxf(tm1, fmaxf(sa[nf][2], sa[nf][3]));
        }
        tm0 = fmaxf(tm0, __shfl_xor_sync(0xffffffffu, tm0, 1));
        tm0 = fmaxf(tm0, __shfl_xor_sync(0xffffffffu, tm0, 2));
        tm1 = fmaxf(tm1, __shfl_xor_sync(0xffffffffu, tm1, 1));
        tm1 = fmaxf(tm1, __shfl_xor_sync(0xffffffffu, tm1, 2));
        float mn0 = fmaxf(m0, tm0), mn1 = fmaxf(m1, tm1);
        float cc0 = __expf(m0 - mn0), cc1 = __expf(m1 - mn1);
        m0 = mn0; m1 = mn1;

        float ls0 = 0.f, ls1 = 0.f;
#pragma unroll
        for (int nf = 0; nf < 8; nf++) {
            float p00 = __expf(sa[nf][0] - mn0);
            float p01 = __expf(sa[nf][1] - mn0);
            float p10 = __expf(sa[nf][2] - mn1);
            float p11 = __expf(sa[nf][3] - mn1);
            ls0 += p00 + p01;
            ls1 += p10 + p11;
            Ph2[(wrow + gid) * ASW + nf * 4 + tig] = __floats2half2_rn(p00, p01);
            Ph2[(wrow + gid + 8) * ASW + nf * 4 + tig] = __floats2half2_rn(p10, p11);
        }
        ls0 += __shfl_xor_sync(0xffffffffu, ls0, 1);
        ls0 += __shfl_xor_sync(0xffffffffu, ls0, 2);
        ls1 += __shfl_xor_sync(0xffffffffu, ls1, 1);
        ls1 += __shfl_xor_sync(0xffffffffu, ls1, 2);
        l0 = l0 * cc0 + ls0;
        l1 = l1 * cc1 + ls1;
#pragma unroll
        for (int nf = 0; nf < 8; nf++) {
            oa[nf][0] *= cc0; oa[nf][1] *= cc0;
            oa[nf][2] *= cc1; oa[nf][3] *= cc1;
        }
        __syncwarp();

        // O += P V  (P A-frags via ldmatrix.x4; V B-frags via ldmatrix.x4.trans)
        int g = lane >> 3, r = lane & 7;
#pragma unroll
        for (int kc = 0; kc < 4; kc++) {
            uint32_t pa = sbP + (wrow + (lane & 15)) * (AS * 2) + kc * 32 + ((lane >> 4) & 1) * 16;
            uint32_t a0, a1, a2, a3;
            ldmatrix_x4(a0, a1, a2, a3, pa);
#pragma unroll
            for (int nf2 = 0; nf2 < 4; nf2++) {
                uint32_t addr = vbase + (kc * 16 + (g & 1) * 8 + r) * (AS * 2)
                                      + nf2 * 32 + (g >> 1) * 16;
                uint32_t r0, r1, r2, r3;
                ldmatrix_x4_t(r0, r1, r2, r3, addr);
                mma_f16(oa[2 * nf2][0], oa[2 * nf2][1], oa[2 * nf2][2], oa[2 * nf2][3],
                        a0, a1, a2, a3, r0, r1);
                mma_f16(oa[2 * nf2 + 1][0], oa[2 * nf2 + 1][1], oa[2 * nf2 + 1][2], oa[2 * nf2 + 1][3],
                        a0, a1, a2, a3, r2, r3);
            }
        }
        __syncwarp();
    }

    float inv0 = 1.f / l0, inv1 = 1.f / l1;
    int r0g = qbase + wrow + gid;
    size_t o0 = ((size_t)(b * NS) + r0g) * ND + h * NDH;
    size_t o1 = o0 + (size_t)8 * ND;
#pragma unroll
    for (int nf = 0; nf < 8; nf++) {
        int col = nf * 8 + 2 * tig;
        float2 x0 = *(const float2*)(x + o0 + col);
        float2 x1 = *(const float2*)(x + o1 + col);
        *(float2*)(out + o0 + col) = make_float2(x0.x + oa[nf][0] * inv0, x0.y + oa[nf][1] * inv0);
        *(float2*)(out + o1 + col) = make_float2(x1.x + oa[nf][2] * inv1, x1.y + oa[nf][3] * inv1);
    }
}

// ---------------- FFN fp16 GEMM: 128x128 tile, Ktile 64, double buffer ------
// smem row stride 72 halves (144B): ldmatrix rows hit banks 4*(r&7) - clean.
#define FS2 72
#define FBUF2 (128 * FS2)                 // halves per matrix buffer
#define GEMM_SMEM (4 * FBUF2 * 2)         // A0,B0,A1,B1 = 73728 B

template <int EPI>
__global__ __launch_bounds__(256) void gemm_h(
    const __half* __restrict__ A, const __half* __restrict__ Bt,
    void* __restrict__ Cv, int K, int N)
{
    extern __shared__ __half sh[];
    uint32_t sb = smem_u32(sh);

    int t = threadIdx.x, w = t >> 5, lane = t & 31;
    int gid = lane >> 2, tig = lane & 3;
    int wm = w >> 2, wn = w & 3;
    int m0 = blockIdx.y * 128, n0 = blockIdx.x * 128;
    int lrow = t >> 3, lc = t & 7;        // coalesced: 8 lanes per 128B row chunk

    const __half* Ag = A + (size_t)m0 * K;
    const __half* Bg = Bt + (size_t)n0 * K;

    float acc[4][4][4];
#pragma unroll
    for (int i = 0; i < 4; i++)
#pragma unroll
        for (int j = 0; j < 4; j++)
#pragma unroll
            for (int r = 0; r < 4; r++) acc[i][j][r] = 0.f;

    int nkt = K >> 6;
    // prefetch kt=0 -> stage 0
    {
        uint32_t dA = sb, dB = sb + FBUF2 * 2;
#pragma unroll
        for (int p = 0; p < 4; p++) {
            int row = lrow + p * 32;
            cp_async16(dA + row * (FS2 * 2) + lc * 16, Ag + (size_t)row * K + lc * 8);
            cp_async16(dB + row * (FS2 * 2) + lc * 16, Bg + (size_t)row * K + lc * 8);
        }
        asm volatile("cp.async.commit_group;" ::: "memory");
    }

    for (int kt = 0; kt < nkt; kt++) {
        int cur = kt & 1, nxt = cur ^ 1;
        __syncthreads();   // all warps finished reading stage nxt
        if (kt + 1 < nkt) {
            uint32_t dA = sb + nxt * (2 * FBUF2 * 2), dB = dA + FBUF2 * 2;
            int kh = (kt + 1) * 64;
#pragma unroll
            for (int p = 0; p < 4; p++) {
                int row = lrow + p * 32;
                cp_async16(dA + row * (FS2 * 2) + lc * 16, Ag + (size_t)row * K + kh + lc * 8);
                cp_async16(dB + row * (FS2 * 2) + lc * 16, Bg + (size_t)row * K + kh + lc * 8);
            }
            asm volatile("cp.async.commit_group;\n\tcp.async.wait_group 1;" ::: "memory");
        } else {
            asm volatile("cp.async.wait_group 0;" ::: "memory");
        }
        __syncthreads();

        uint32_t Ab = sb + cur * (2 * FBUF2 * 2);
        uint32_t Bb = Ab + FBUF2 * 2;

#pragma unroll
        for (int ks = 0; ks < 4; ks++) {
            uint32_t a[4][4];
#pragma unroll
            for (int mf = 0; mf < 4; mf++) {
                int arow = wm * 64 + mf * 16 + (lane & 15);
                uint32_t addr = Ab + arow * (FS2 * 2) + ks * 32 + ((lane >> 4) & 1) * 16;
                ldmatrix_x4(a[mf][0], a[mf][1], a[mf][2], a[mf][3], addr);
            }
            uint32_t bb[4][2];
#pragma unroll
            for (int nf2 = 0; nf2 < 2; nf2++) {
                int brow = wn * 32 + (2 * nf2 + ((lane >> 4) & 1)) * 8 + (lane & 7);
                uint32_t addr = Bb + brow * (FS2 * 2) + ks * 32 + ((lane >> 3) & 1) * 16;
                ldmatrix_x4(bb[2 * nf2][0], bb[2 * nf2][1],
                            bb[2 * nf2 + 1][0], bb[2 * nf2 + 1][1], addr);
            }
#pragma unroll
            for (int mf = 0; mf < 4; mf++)
#pragma unroll
                for (int nf = 0; nf < 4; nf++)
                    mma_f16(acc[mf][nf][0], acc[mf][nf][1], acc[mf][nf][2], acc[mf][nf][3],
                            a[mf][0], a[mf][1], a[mf][2], a[mf][3],
                            bb[nf][0], bb[nf][1]);
        }
    }

#pragma unroll
    for (int mf = 0; mf < 4; mf++) {
#pragma unroll
        for (int nf = 0; nf < 4; nf++) {
            int row = m0 + wm * 64 + mf * 16 + gid;
            int col = n0 + wn * 32 + nf * 8 + tig * 2;
            if (EPI == 0) {
                __half2* C = (__half2*)Cv;
                C[(size_t)row * (N / 2) + col / 2] =
                    __floats2half2_rn(gelu_exact(acc[mf][nf][0]), gelu_exact(acc[mf][nf][1]));
                C[(size_t)(row + 8) * (N / 2) + col / 2] =
                    __floats2half2_rn(gelu_exact(acc[mf][nf][2]), gelu_exact(acc[mf][nf][3]));
            } else {
                float* C = (float*)Cv;
                float* p0 = C + (size_t)row * N + col;
                float* p1 = C + (size_t)(row + 8) * N + col;
                float2 c0v = *(float2*)p0, c1v = *(float2*)p1;
                *(float2*)p0 = make_float2(c0v.x + acc[mf][nf][0], c0v.y + acc[mf][nf][1]);
                *(float2*)p1 = make_float2(c1v.x + acc[mf][nf][2], c1v.y + acc[mf][nf][3]);
            }
        }
    }
}

// ---------------- host launcher ---------------------------------------------
extern "C" void kernel_launch(void* const* d_in, const int* in_sizes, int n_in,
                              void* d_out, int out_size)
{
    const float* x     = (const float*)d_in[0];
    const float* ln1_g = (const float*)d_in[1];
    const float* ln1_b = (const float*)d_in[2];
    const float* Wq    = (const float*)d_in[3];
    const float* bq    = (const float*)d_in[4];
    const float* Wk    = (const float*)d_in[5];
    const float* bk    = (const float*)d_in[6];
    const float* Wv    = (const float*)d_in[7];
    const float* bv    = (const float*)d_in[8];
    const float* ln2_g = (const float*)d_in[9];
    const float* ln2_b = (const float*)d_in[10];
    const float* W1    = (const float*)d_in[11];
    const float* W2    = (const float*)d_in[12];
    float* out = (float*)d_out;

    __half *ln1p, *qp, *kp, *vp, *ln2p, *hidp, *w1tp, *w2tp, *wqkvp;
    cudaGetSymbolAddress((void**)&ln1p,  g_ln1h);
    cudaGetSymbolAddress((void**)&qp,    g_qh);
    cudaGetSymbolAddress((void**)&kp,    g_kh);
    cudaGetSymbolAddress((void**)&vp,    g_vh);
    cudaGetSymbolAddress((void**)&ln2p,  g_ln2h);
    cudaGetSymbolAddress((void**)&hidp,  g_hidh);
    cudaGetSymbolAddress((void**)&w1tp,  g_w1th);
    cudaGetSymbolAddress((void**)&w2tp,  g_w2th);
    cudaGetSymbolAddress((void**)&wqkvp, g_wqkvh);

    cudaFuncSetAttribute(qkv_mma,   cudaFuncAttributeMaxDynamicSharedMemorySize, QKV_SMEM);
    cudaFuncSetAttribute(attn_h,    cudaFuncAttributeMaxDynamicSharedMemorySize, ATTN_SMEM);
    cudaFuncSetAttribute(gemm_h<0>, cudaFuncAttributeMaxDynamicSharedMemorySize, GEMM_SMEM);
    cudaFuncSetAttribute(gemm_h<1>, cudaFuncAttributeMaxDynamicSharedMemorySize, GEMM_SMEM);

    // weight preps
    transpose_f16<<<dim3(DFF / 32, ND / 32), 256>>>(W1, w1tp, ND, DFF);   // [3072][768]
    transpose_f16<<<dim3(ND / 32, DFF / 32), 256>>>(W2, w2tp, DFF, ND);   // [768][3072]
    wqkv_prep<<<dim3(NH, 3), 256>>>(Wq, Wk, Wv, wqkvp);
    // LN1 -> fp16
    ln_half<<<NROWS, 256>>>(x, ln1_g, ln1_b, ln1p);
    // QKV (fp16 mma, Q pre-scaled by 1/8)
    qkv_mma<<<dim3(NB * NH, NS / 128), 256, QKV_SMEM>>>(ln1p, wqkvp, bq, bk, bv, qp, kp, vp);
    // attention + residual (out = x + msa)
    attn_h<<<dim3(NB * NH, NS / 128), 256, ATTN_SMEM>>>(qp, kp, vp, x, out);
    // LN2 -> fp16
    ln_half<<<NROWS, 256>>>(out, ln2_g, ln2_b, ln2p);
    // FFN up + GELU -> fp16 hid
    gemm_h<0><<<dim3(DFF / 128, NROWS / 128), 256, GEMM_SMEM>>>(ln2p, w1tp, (void*)hidp, ND, DFF);
    // FFN down + residual into out
    gemm_h<1><<<dim3(ND / 128, NROWS / 128), 256, GEMM_SMEM>>>(hidp, w2tp, (void*)out, DFF, ND);
}

// round 16
// speedup vs baseline: 7.3026x; 1.0382x over previous
#include <cuda_runtime.h>
#include <cuda_fp16.h>
#include <math.h>
#include <stdint.h>

// Problem constants: B=8, S=1024, D=768, H=12, DH=64
#define NB 8
#define NS 1024
#define ND 768
#define NH 12
#define NDH 64
#define NROWS (NB * NS)          // 8192
#define DFF (4 * ND)             // 3072

// ---------------- scratch (device globals) ----------------------------------
__device__ __half g_ln1h[NROWS * ND];
__device__ __half g_qh[NROWS * ND];
__device__ __half g_kh[NROWS * ND];
__device__ __half g_vh[NROWS * ND];
__device__ __half g_ln2h[NROWS * ND];
__device__ __half g_hidh[(size_t)NROWS * DFF];     // 48 MB
__device__ __half g_w1th[DFF * ND];                // W1^T [3072][768]
__device__ __half g_w2th[ND * DFF];                // W2^T [768][3072]
__device__ __half g_wqkvh[3 * NH * 64 * 64];       // per-head W^T [mat][h][e][d]

// ---------------- helpers ----------------------------------------------------
__device__ __forceinline__ uint32_t smem_u32(const void* p) {
    uint32_t a;
    asm("{ .reg .u64 t; cvta.to.shared.u64 t, %1; cvt.u32.u64 %0, t; }" : "=r"(a) : "l"(p));
    return a;
}
__device__ __forceinline__ void cp_async16(uint32_t s, const void* g) {
    asm volatile("cp.async.cg.shared.global [%0], [%1], 16;" :: "r"(s), "l"(g));
}
__device__ __forceinline__ void mma_f16(
    float& c0, float& c1, float& c2, float& c3,
    uint32_t a0, uint32_t a1, uint32_t a2, uint32_t a3,
    uint32_t b0, uint32_t b1)
{
    asm volatile(
        "mma.sync.aligned.m16n8k16.row.col.f32.f16.f16.f32 "
        "{%0,%1,%2,%3}, {%4,%5,%6,%7}, {%8,%9}, {%0,%1,%2,%3};"
        : "+f"(c0), "+f"(c1), "+f"(c2), "+f"(c3)
        : "r"(a0), "r"(a1), "r"(a2), "r"(a3), "r"(b0), "r"(b1));
}
__device__ __forceinline__ void ldmatrix_x4(
    uint32_t& r0, uint32_t& r1, uint32_t& r2, uint32_t& r3, uint32_t addr)
{
    asm volatile("ldmatrix.sync.aligned.m8n8.x4.shared.b16 {%0,%1,%2,%3}, [%4];"
        : "=r"(r0), "=r"(r1), "=r"(r2), "=r"(r3) : "r"(addr));
}
__device__ __forceinline__ void ldmatrix_x4_t(
    uint32_t& r0, uint32_t& r1, uint32_t& r2, uint32_t& r3, uint32_t addr)
{
    asm volatile("ldmatrix.sync.aligned.m8n8.x4.trans.shared.b16 {%0,%1,%2,%3}, [%4];"
        : "=r"(r0), "=r"(r1), "=r"(r2), "=r"(r3) : "r"(addr));
}
__device__ __forceinline__ float gelu_exact(float x) {
    return 0.5f * x * (1.0f + erff(x * 0.70710678118654752f));
}
__device__ __forceinline__ uint32_t pack_h2(float a, float b) {
    __half2 h = __floats2half2_rn(a, b);
    return *(uint32_t*)&h;
}

// ---------------- LayerNorm: one warp per row, fp16 output -------------------
__global__ __launch_bounds__(256) void ln_half(
    const float* __restrict__ x, const float* __restrict__ gw,
    const float* __restrict__ bw, __half* __restrict__ out)
{
    int wid = threadIdx.x >> 5, lane = threadIdx.x & 31;
    int row = blockIdx.x * 8 + wid;
    const float4* xr = (const float4*)(x + (size_t)row * ND);

    float4 v[6];
    float s = 0.f;
#pragma unroll
    for (int i = 0; i < 6; i++) {
        v[i] = xr[lane + 32 * i];
        s += v[i].x + v[i].y + v[i].z + v[i].w;
    }
#pragma unroll
    for (int o = 16; o > 0; o >>= 1) s += __shfl_xor_sync(0xffffffffu, s, o);
    float mean = s * (1.0f / (float)ND);

    float sq = 0.f;
#pragma unroll
    for (int i = 0; i < 6; i++) {
        float a = v[i].x - mean, b = v[i].y - mean, c = v[i].z - mean, d = v[i].w - mean;
        sq += a * a + b * b + c * c + d * d;
    }
#pragma unroll
    for (int o = 16; o > 0; o >>= 1) sq += __shfl_xor_sync(0xffffffffu, sq, o);
    float rstd = rsqrtf(sq * (1.0f / (float)ND) + 1e-5f);

    const float4* g4 = (const float4*)gw;
    const float4* b4 = (const float4*)bw;
    __half2* orow = (__half2*)(out + (size_t)row * ND);
#pragma unroll
    for (int i = 0; i < 6; i++) {
        int f = lane + 32 * i;
        float4 g = g4[f], b = b4[f];
        float o0 = (v[i].x - mean) * rstd * g.x + b.x;
        float o1 = (v[i].y - mean) * rstd * g.y + b.y;
        float o2 = (v[i].z - mean) * rstd * g.z + b.z;
        float o3 = (v[i].w - mean) * rstd * g.w + b.w;
        orow[f * 2]     = __floats2half2_rn(o0, o1);
        orow[f * 2 + 1] = __floats2half2_rn(o2, o3);
    }
}

// ---------------- transpose fp32 -> fp16: in[R][C] -> out[C][R] --------------
__global__ __launch_bounds__(256) void transpose_f16(
    const float* __restrict__ in, __half* __restrict__ out, int R, int C)
{
    __shared__ float tile[32][33];
    int c0 = blockIdx.x * 32, r0 = blockIdx.y * 32;
    int tx = threadIdx.x & 31, ty = threadIdx.x >> 5;
#pragma unroll
    for (int i = 0; i < 32; i += 8)
        tile[ty + i][tx] = in[(size_t)(r0 + ty + i) * C + c0 + tx];
    __syncthreads();
#pragma unroll
    for (int i = 0; i < 32; i += 8)
        out[(size_t)(c0 + ty + i) * R + r0 + tx] = __float2half_rn(tile[tx][ty + i]);
}

// ---------------- per-head weight transpose: W[h][d][e] -> half [m][h][e][d] -
__global__ __launch_bounds__(256) void wqkv_prep(
    const float* __restrict__ Wq, const float* __restrict__ Wk,
    const float* __restrict__ Wv, __half* __restrict__ out)
{
    int h = blockIdx.x, m = blockIdx.y;
    const float* W = (m == 0) ? Wq : ((m == 1) ? Wk : Wv);
    W += (size_t)h * 4096;
    __half* o = out + ((size_t)m * NH + h) * 4096;
    for (int idx = threadIdx.x; idx < 4096; idx += 256) {
        int d = idx >> 6, e = idx & 63;
        o[e * 64 + d] = __float2half_rn(W[d * 64 + e]);
    }
}

// ---------------- QKV: fp16 mma, CTA = 128 rows x 1 head --------------------
#define QS 72
#define QSW 36
#define QKV_SMEM ((128 * QS + 3 * 64 * QS) * 2)   // 46080 B

__global__ __launch_bounds__(256) void qkv_mma(
    const __half* __restrict__ ln1, const __half* __restrict__ wt,
    const float* __restrict__ bq, const float* __restrict__ bk,
    const float* __restrict__ bv,
    __half* __restrict__ q, __half* __restrict__ k, __half* __restrict__ v)
{
    extern __shared__ __half sh[];
    uint32_t sb = smem_u32(sh);
    uint32_t aW = sb + 128 * QS * 2;

    int bh = blockIdx.x;
    int h = bh % NH, b = bh / NH;
    int s0 = blockIdx.y * 128;
    int t = threadIdx.x, w = t >> 5, lane = t & 31;
    int gid = lane >> 2, tig = lane & 3;
    int rowb = (t & 7) + 8 * (t >> 5);
    int c0 = (t >> 3) & 3;

    const __half* Abase = ln1 + ((size_t)(b * NS + s0)) * ND + h * 64;
#pragma unroll
    for (int i = 0; i < 4; i++) {
        int row = rowb + 64 * (i >> 1);
        int c = c0 + 4 * (i & 1);
        cp_async16(sb + row * (QS * 2) + c * 16, Abase + (size_t)row * ND + c * 8);
    }
    const __half* Wbase = wt + (size_t)h * 4096;
#pragma unroll
    for (int m = 0; m < 3; m++)
#pragma unroll
        for (int i = 0; i < 2; i++) {
            int c = c0 + 4 * i;
            cp_async16(aW + m * (64 * QS * 2) + rowb * (QS * 2) + c * 16,
                       Wbase + (size_t)m * (NH * 4096) + rowb * 64 + c * 8);
        }
    asm volatile("cp.async.commit_group;\n\tcp.async.wait_group 0;" ::: "memory");
    __syncthreads();

    const uint32_t* Au = (const uint32_t*)sh;
    const uint32_t* Wu = (const uint32_t*)(sh + 128 * QS);
    int wrow = w * 16;

    uint32_t af[4][4];
#pragma unroll
    for (int kc = 0; kc < 4; kc++) {
        af[kc][0] = Au[(wrow + gid) * QSW + kc * 8 + tig];
        af[kc][1] = Au[(wrow + gid + 8) * QSW + kc * 8 + tig];
        af[kc][2] = Au[(wrow + gid) * QSW + kc * 8 + 4 + tig];
        af[kc][3] = Au[(wrow + gid + 8) * QSW + kc * 8 + 4 + tig];
    }
    float acc[3][8][4];
#pragma unroll
    for (int m = 0; m < 3; m++)
#pragma unroll
        for (int nf = 0; nf < 8; nf++)
#pragma unroll
            for (int r = 0; r < 4; r++) acc[m][nf][r] = 0.f;

#pragma unroll
    for (int kc = 0; kc < 4; kc++)
#pragma unroll
        for (int m = 0; m < 3; m++)
#pragma unroll
            for (int nf = 0; nf < 8; nf++) {
                uint32_t b0 = Wu[m * (64 * QSW) + (nf * 8 + gid) * QSW + kc * 8 + tig];
                uint32_t b1 = Wu[m * (64 * QSW) + (nf * 8 + gid) * QSW + kc * 8 + 4 + tig];
                mma_f16(acc[m][nf][0], acc[m][nf][1], acc[m][nf][2], acc[m][nf][3],
                        af[kc][0], af[kc][1], af[kc][2], af[kc][3], b0, b1);
            }

    size_t grow0 = (size_t)bh * NS + s0 + wrow + gid;
    size_t grow1 = grow0 + 8;
    const float* biases[3] = { bq + h * 64, bk + h * 64, bv + h * 64 };
    __half* dsts[3] = { q, k, v };
#pragma unroll
    for (int m = 0; m < 3; m++) {
        __half2* D = (__half2*)dsts[m];
        const float* bi = biases[m];
#pragma unroll
        for (int nf = 0; nf < 8; nf++) {
            int col = nf * 8 + 2 * tig;
            float b0 = bi[col], b1 = bi[col + 1];
            float v00 = acc[m][nf][0] + b0, v01 = acc[m][nf][1] + b1;
            float v10 = acc[m][nf][2] + b0, v11 = acc[m][nf][3] + b1;
            if (m == 0) { v00 *= 0.125f; v01 *= 0.125f; v10 *= 0.125f; v11 *= 0.125f; }
            D[grow0 * 32 + nf * 4 + tig] = __floats2half2_rn(v00, v01);
            D[grow1 * 32 + nf * 4 + tig] = __floats2half2_rn(v10, v11);
        }
    }
}

// ---------------- Attention: fp16 mma flash, register-resident P ------------
// smem layout (halves): K0,K1 [64*AS each] | V0,V1 [64*AS each]. No P buffer:
// the S accumulator C-fragment layout IS the PV A-fragment layout, so exp()
// results are packed directly into A-frags (verified vs round-9 LDS indices).
#define AS 72
#define ATTN_SMEM ((4 * 64 * AS) * 2)   // 36864 B

__global__ __launch_bounds__(256) void attn_h(
    const __half* __restrict__ q, const __half* __restrict__ k,
    const __half* __restrict__ v, const float* __restrict__ x,
    float* __restrict__ out)
{
    extern __shared__ __half sh[];
    uint32_t sb = smem_u32(sh);

    int bh = blockIdx.x;
    int h = bh % NH, b = bh / NH;
    int t = threadIdx.x, w = t >> 5, lane = t & 31;
    int gid = lane >> 2, tig = lane & 3;
    int qbase = blockIdx.y * 128;
    int wrow = w * 16;

    // Q fragments (pre-scaled by 1/8 in qkv_mma)
    uint32_t qf[4][4];
    {
        const uint32_t* Qu = (const uint32_t*)(q + ((size_t)bh * NS + qbase + wrow) * NDH);
#pragma unroll
        for (int kc = 0; kc < 4; kc++) {
            qf[kc][0] = Qu[gid * 32 + kc * 8 + tig];
            qf[kc][1] = Qu[(gid + 8) * 32 + kc * 8 + tig];
            qf[kc][2] = Qu[gid * 32 + kc * 8 + 4 + tig];
            qf[kc][3] = Qu[(gid + 8) * 32 + kc * 8 + 4 + tig];
        }
    }

    float oa[8][4];
#pragma unroll
    for (int nf = 0; nf < 8; nf++) { oa[nf][0] = oa[nf][1] = oa[nf][2] = oa[nf][3] = 0.f; }
    float m0 = -1e30f, m1 = -1e30f, l0 = 0.f, l1 = 0.f;

    const __half* Kg0 = k + (size_t)bh * NS * NDH;
    const __half* Vg0 = v + (size_t)bh * NS * NDH;
    int lrow = t >> 3, lc = t & 7;

    // prefetch tile 0 into stage 0
    {
#pragma unroll
        for (int p = 0; p < 2; p++) {
            int row = lrow + p * 32;
            cp_async16(sb + row * (AS * 2) + lc * 16, Kg0 + (size_t)row * NDH + lc * 8);
            cp_async16(sb + (2 * 64 * AS) * 2 + row * (AS * 2) + lc * 16,
                       Vg0 + (size_t)row * NDH + lc * 8);
        }
        asm volatile("cp.async.commit_group;" ::: "memory");
    }

    for (int kt = 0; kt < 16; kt++) {
        int cur = kt & 1, nxt = cur ^ 1;
        __syncthreads();
        if (kt + 1 < 16) {
            const __half* Kg = Kg0 + (size_t)(kt + 1) * 64 * NDH;
            const __half* Vg = Vg0 + (size_t)(kt + 1) * 64 * NDH;
            uint32_t kb = sb + nxt * (64 * AS * 2);
            uint32_t vb = sb + (2 * 64 * AS) * 2 + nxt * (64 * AS * 2);
#pragma unroll
            for (int p = 0; p < 2; p++) {
                int row = lrow + p * 32;
                cp_async16(kb + row * (AS * 2) + lc * 16, Kg + (size_t)row * NDH + lc * 8);
                cp_async16(vb + row * (AS * 2) + lc * 16, Vg + (size_t)row * NDH + lc * 8);
            }
            asm volatile("cp.async.commit_group;\n\tcp.async.wait_group 1;" ::: "memory");
        } else {
            asm volatile("cp.async.wait_group 0;" ::: "memory");
        }
        __syncthreads();

        uint32_t kbase = sb + cur * (64 * AS * 2);
        uint32_t vbase = sb + (2 * 64 * AS) * 2 + cur * (64 * AS * 2);

        // S = (Q/8) K^T  (K B-frags via ldmatrix.x4, 2 n-tiles per load)
        float sa[8][4];
#pragma unroll
        for (int nf = 0; nf < 8; nf++) { sa[nf][0] = sa[nf][1] = sa[nf][2] = sa[nf][3] = 0.f; }
#pragma unroll
        for (int kc = 0; kc < 4; kc++)
#pragma unroll
            for (int nf2 = 0; nf2 < 4; nf2++) {
                int nrow = (2 * nf2 + ((lane >> 4) & 1)) * 8 + (lane & 7);
                uint32_t addr = kbase + nrow * (AS * 2) + kc * 32 + ((lane >> 3) & 1) * 16;
                uint32_t b0, b1, b2, b3;
                ldmatrix_x4(b0, b1, b2, b3, addr);
                mma_f16(sa[2 * nf2][0], sa[2 * nf2][1], sa[2 * nf2][2], sa[2 * nf2][3],
                        qf[kc][0], qf[kc][1], qf[kc][2], qf[kc][3], b0, b1);
                mma_f16(sa[2 * nf2 + 1][0], sa[2 * nf2 + 1][1], sa[2 * nf2 + 1][2], sa[2 * nf2 + 1][3],
                        qf[kc][0], qf[kc][1], qf[kc][2], qf[kc][3], b2, b3);
            }

        // online softmax (rows gid / gid+8)
        float tm0 = -1e30f, tm1 = -1e30f;
#pragma unroll
        for (int nf = 0; nf < 8; nf++) {
            tm0 = fmaxf(tm0, fmaxf(sa[nf][0], sa[nf][1]));
            tm1 = fmaxf(tm1, fmaxf(sa[nf][2], sa[nf][3]));
        }
        tm0 = fmaxf(tm0, __shfl_xor_sync(0xffffffffu, tm0, 1));
        tm0 = fmaxf(tm0, __shfl_xor_sync(0xffffffffu, tm0, 2));
        tm1 = fmaxf(tm1, __shfl_xor_sync(0xffffffffu, tm1, 1));
        tm1 = fmaxf(tm1, __shfl_xor_sync(0xffffffffu, tm1, 2));
        float mn0 = fmaxf(m0, tm0), mn1 = fmaxf(m1, tm1);
        float cc0 = __expf(m0 - mn0), cc1 = __expf(m1 - mn1);
        m0 = mn0; m1 = mn1;

        // exp + pack P directly into PV A-fragments (no smem round trip)
        uint32_t pf[4][4];
        float ls0 = 0.f, ls1 = 0.f;
#pragma unroll
        for (int kc = 0; kc < 4; kc++) {
            int nf = 2 * kc;
            float p00 = __expf(sa[nf][0] - mn0);
            float p01 = __expf(sa[nf][1] - mn0);
            float p10 = __expf(sa[nf][2] - mn1);
            float p11 = __expf(sa[nf][3] - mn1);
            float q00 = __expf(sa[nf + 1][0] - mn0);
            float q01 = __expf(sa[nf + 1][1] - mn0);
            float q10 = __expf(sa[nf + 1][2] - mn1);
            float q11 = __expf(sa[nf + 1][3] - mn1);
            ls0 += p00 + p01 + q00 + q01;
            ls1 += p10 + p11 + q10 + q11;
            pf[kc][0] = pack_h2(p00, p01);   // row gid,   k = 16kc+2tig(+1)
            pf[kc][1] = pack_h2(p10, p11);   // row gid+8, same k
            pf[kc][2] = pack_h2(q00, q01);   // row gid,   k = 16kc+8+2tig(+1)
            pf[kc][3] = pack_h2(q10, q11);   // row gid+8, same k
        }
        ls0 += __shfl_xor_sync(0xffffffffu, ls0, 1);
        ls0 += __shfl_xor_sync(0xffffffffu, ls0, 2);
        ls1 += __shfl_xor_sync(0xffffffffu, ls1, 1);
        ls1 += __shfl_xor_sync(0xffffffffu, ls1, 2);
        l0 = l0 * cc0 + ls0;
        l1 = l1 * cc1 + ls1;
#pragma unroll
        for (int nf = 0; nf < 8; nf++) {
            oa[nf][0] *= cc0; oa[nf][1] *= cc0;
            oa[nf][2] *= cc1; oa[nf][3] *= cc1;
        }

        // O += P V  (V B-frags via ldmatrix.x4.trans)
        int g = lane >> 3, r = lane & 7;
#pragma unroll
        for (int kc = 0; kc < 4; kc++) {
#pragma unroll
            for (int nf2 = 0; nf2 < 4; nf2++) {
                uint32_t addr = vbase + (kc * 16 + (g & 1) * 8 + r) * (AS * 2)
                                      + nf2 * 32 + (g >> 1) * 16;
                uint32_t r0, r1, r2, r3;
                ldmatrix_x4_t(r0, r1, r2, r3, addr);
                mma_f16(oa[2 * nf2][0], oa[2 * nf2][1], oa[2 * nf2][2], oa[2 * nf2][3],
                        pf[kc][0], pf[kc][1], pf[kc][2], pf[kc][3], r0, r1);
                mma_f16(oa[2 * nf2 + 1][0], oa[2 * nf2 + 1][1], oa[2 * nf2 + 1][2], oa[2 * nf2 + 1][3],
                        pf[kc][0], pf[kc][1], pf[kc][2], pf[kc][3], r2, r3);
            }
        }
    }

    float inv0 = 1.f / l0, inv1 = 1.f / l1;
    int r0g = qbase + wrow + gid;
    size_t o0 = ((size_t)(b * NS) + r0g) * ND + h * NDH;
    size_t o1 = o0 + (size_t)8 * ND;
#pragma unroll
    for (int nf = 0; nf < 8; nf++) {
        int col = nf * 8 + 2 * tig;
        float2 x0 = *(const float2*)(x + o0 + col);
        float2 x1 = *(const float2*)(x + o1 + col);
        *(float2*)(out + o0 + col) = make_float2(x0.x + oa[nf][0] * inv0, x0.y + oa[nf][1] * inv0);
        *(float2*)(out + o1 + col) = make_float2(x1.x + oa[nf][2] * inv1, x1.y + oa[nf][3] * inv1);
    }
}

// ---------------- FFN fp16 GEMM: 128x128 tile, Ktile 64, double buffer ------
#define FS2 72
#define FBUF2 (128 * FS2)                 // halves per matrix buffer
#define GEMM_SMEM (4 * FBUF2 * 2)         // A0,B0,A1,B1 = 73728 B

template <int EPI>
__global__ __launch_bounds__(256) void gemm_h(
    const __half* __restrict__ A, const __half* __restrict__ Bt,
    void* __restrict__ Cv, int K, int N)
{
    extern __shared__ __half sh[];
    uint32_t sb = smem_u32(sh);

    int t = threadIdx.x, w = t >> 5, lane = t & 31;
    int gid = lane >> 2, tig = lane & 3;
    int wm = w >> 2, wn = w & 3;
    int m0 = blockIdx.y * 128, n0 = blockIdx.x * 128;
    int lrow = t >> 3, lc = t & 7;

    const __half* Ag = A + (size_t)m0 * K;
    const __half* Bg = Bt + (size_t)n0 * K;

    float acc[4][4][4];
#pragma unroll
    for (int i = 0; i < 4; i++)
#pragma unroll
        for (int j = 0; j < 4; j++)
#pragma unroll
            for (int r = 0; r < 4; r++) acc[i][j][r] = 0.f;

    int nkt = K >> 6;
    {
        uint32_t dA = sb, dB = sb + FBUF2 * 2;
#pragma unroll
        for (int p = 0; p < 4; p++) {
            int row = lrow + p * 32;
            cp_async16(dA + row * (FS2 * 2) + lc * 16, Ag + (size_t)row * K + lc * 8);
            cp_async16(dB + row * (FS2 * 2) + lc * 16, Bg + (size_t)row * K + lc * 8);
        }
        asm volatile("cp.async.commit_group;" ::: "memory");
    }

    for (int kt = 0; kt < nkt; kt++) {
        int cur = kt & 1, nxt = cur ^ 1;
        __syncthreads();
        if (kt + 1 < nkt) {
            uint32_t dA = sb + nxt * (2 * FBUF2 * 2), dB = dA + FBUF2 * 2;
            int kh = (kt + 1) * 64;
#pragma unroll
            for (int p = 0; p < 4; p++) {
                int row = lrow + p * 32;
                cp_async16(dA + row * (FS2 * 2) + lc * 16, Ag + (size_t)row * K + kh + lc * 8);
                cp_async16(dB + row * (FS2 * 2) + lc * 16, Bg + (size_t)row * K + kh + lc * 8);
            }
            asm volatile("cp.async.commit_group;\n\tcp.async.wait_group 1;" ::: "memory");
        } else {
            asm volatile("cp.async.wait_group 0;" ::: "memory");
        }
        __syncthreads();

        uint32_t Ab = sb + cur * (2 * FBUF2 * 2);
        uint32_t Bb = Ab + FBUF2 * 2;

#pragma unroll
        for (int ks = 0; ks < 4; ks++) {
            uint32_t a[4][4];
#pragma unroll
            for (int mf = 0; mf < 4; mf++) {
                int arow = wm * 64 + mf * 16 + (lane & 15);
                uint32_t addr = Ab + arow * (FS2 * 2) + ks * 32 + ((lane >> 4) & 1) * 16;
                ldmatrix_x4(a[mf][0], a[mf][1], a[mf][2], a[mf][3], addr);
            }
            uint32_t bb[4][2];
#pragma unroll
            for (int nf2 = 0; nf2 < 2; nf2++) {
                int brow = wn * 32 + (2 * nf2 + ((lane >> 4) & 1)) * 8 + (lane & 7);
                uint32_t addr = Bb + brow * (FS2 * 2) + ks * 32 + ((lane >> 3) & 1) * 16;
                ldmatrix_x4(bb[2 * nf2][0], bb[2 * nf2][1],
                            bb[2 * nf2 + 1][0], bb[2 * nf2 + 1][1], addr);
            }
#pragma unroll
            for (int mf = 0; mf < 4; mf++)
#pragma unroll
                for (int nf = 0; nf < 4; nf++)
                    mma_f16(acc[mf][nf][0], acc[mf][nf][1], acc[mf][nf][2], acc[mf][nf][3],
                            a[mf][0], a[mf][1], a[mf][2], a[mf][3],
                            bb[nf][0], bb[nf][1]);
        }
    }

#pragma unroll
    for (int mf = 0; mf < 4; mf++) {
#pragma unroll
        for (int nf = 0; nf < 4; nf++) {
            int row = m0 + wm * 64 + mf * 16 + gid;
            int col = n0 + wn * 32 + nf * 8 + tig * 2;
            if (EPI == 0) {
                __half2* C = (__half2*)Cv;
                C[(size_t)row * (N / 2) + col / 2] =
                    __floats2half2_rn(gelu_exact(acc[mf][nf][0]), gelu_exact(acc[mf][nf][1]));
                C[(size_t)(row + 8) * (N / 2) + col / 2] =
                    __floats2half2_rn(gelu_exact(acc[mf][nf][2]), gelu_exact(acc[mf][nf][3]));
            } else {
                float* C = (float*)Cv;
                float* p0 = C + (size_t)row * N + col;
                float* p1 = C + (size_t)(row + 8) * N + col;
                float2 c0v = *(float2*)p0, c1v = *(float2*)p1;
                *(float2*)p0 = make_float2(c0v.x + acc[mf][nf][0], c0v.y + acc[mf][nf][1]);
                *(float2*)p1 = make_float2(c1v.x + acc[mf][nf][2], c1v.y + acc[mf][nf][3]);
            }
        }
    }
}

// ---------------- host launcher ---------------------------------------------
extern "C" void kernel_launch(void* const* d_in, const int* in_sizes, int n_in,
                              void* d_out, int out_size)
{
    const float* x     = (const float*)d_in[0];
    const float* ln1_g = (const float*)d_in[1];
    const float* ln1_b = (const float*)d_in[2];
    const float* Wq    = (const float*)d_in[3];
    const float* bq    = (const float*)d_in[4];
    const float* Wk    = (const float*)d_in[5];
    const float* bk    = (const float*)d_in[6];
    const float* Wv    = (const float*)d_in[7];
    const float* bv    = (const float*)d_in[8];
    const float* ln2_g = (const float*)d_in[9];
    const float* ln2_b = (const float*)d_in[10];
    const float* W1    = (const float*)d_in[11];
    const float* W2    = (const float*)d_in[12];
    float* out = (float*)d_out;

    __half *ln1p, *qp, *kp, *vp, *ln2p, *hidp, *w1tp, *w2tp, *wqkvp;
    cudaGetSymbolAddress((void**)&ln1p,  g_ln1h);
    cudaGetSymbolAddress((void**)&qp,    g_qh);
    cudaGetSymbolAddress((void**)&kp,    g_kh);
    cudaGetSymbolAddress((void**)&vp,    g_vh);
    cudaGetSymbolAddress((void**)&ln2p,  g_ln2h);
    cudaGetSymbolAddress((void**)&hidp,  g_hidh);
    cudaGetSymbolAddress((void**)&w1tp,  g_w1th);
    cudaGetSymbolAddress((void**)&w2tp,  g_w2th);
    cudaGetSymbolAddress((void**)&wqkvp, g_wqkvh);

    cudaFuncSetAttribute(qkv_mma,   cudaFuncAttributeMaxDynamicSharedMemorySize, QKV_SMEM);
    cudaFuncSetAttribute(attn_h,    cudaFuncAttributeMaxDynamicSharedMemorySize, ATTN_SMEM);
    cudaFuncSetAttribute(gemm_h<0>, cudaFuncAttributeMaxDynamicSharedMemorySize, GEMM_SMEM);
    cudaFuncSetAttribute(gemm_h<1>, cudaFuncAttributeMaxDynamicSharedMemorySize, GEMM_SMEM);

    // weight preps
    transpose_f16<<<dim3(DFF / 32, ND / 32), 256>>>(W1, w1tp, ND, DFF);   // [3072][768]
    transpose_f16<<<dim3(ND / 32, DFF / 32), 256>>>(W2, w2tp, DFF, ND);   // [768][3072]
    wqkv_prep<<<dim3(NH, 3), 256>>>(Wq, Wk, Wv, wqkvp);
    // LN1 -> fp16 (warp per row)
    ln_half<<<NROWS / 8, 256>>>(x, ln1_g, ln1_b, ln1p);
    // QKV (fp16 mma, Q pre-scaled by 1/8)
    qkv_mma<<<dim3(NB * NH, NS / 128), 256, QKV_SMEM>>>(ln1p, wqkvp, bq, bk, bv, qp, kp, vp);
    // attention + residual (out = x + msa)
    attn_h<<<dim3(NB * NH, NS / 128), 256, ATTN_SMEM>>>(qp, kp, vp, x, out);
    // LN2 -> fp16
    ln_half<<<NROWS / 8, 256>>>(out, ln2_g, ln2_b, ln2p);
    // FFN up + GELU -> fp16 hid
    gemm_h<0><<<dim3(DFF / 128, NROWS / 128), 256, GEMM_SMEM>>>(ln2p, w1tp, (void*)hidp, ND, DFF);
    // FFN down + residual into out
    gemm_h<1><<<dim3(ND / 128, NROWS / 128), 256, GEMM_SMEM>>>(hidp, w2tp, (void*)out, DFF, ND);
}